// round 1
// baseline (speedup 1.0000x reference)
#include <cuda_runtime.h>
#include <cuda_bf16.h>
#include <math.h>

// Problem constants (fixed by reference setup_inputs)
#define BB   4
#define SS   2048
#define DD   1024
#define HH   16
#define HDIM 64
#define MM   (BB*SS)          // 8192

#define NEG_BIG (-1e30f)

// Scratch (device globals: allocation-free rule)
__device__ float g_xn[MM*DD];
__device__ float g_q [MM*DD];   // [B,H,S,Hd]
__device__ float g_k [MM*DD];
__device__ float g_v [MM*DD];
__device__ float g_ao[MM*DD];   // [B,S,D]

// ---------------------------------------------------------------------------
// LayerNorm: one block per row, 256 threads, float4
// ---------------------------------------------------------------------------
__global__ __launch_bounds__(256) void ln_kernel(
    const float* __restrict__ x,
    const float* __restrict__ gamma,
    const float* __restrict__ beta)
{
    int row = blockIdx.x;
    int tid = threadIdx.x;
    const float4* xr = (const float4*)(x + (size_t)row * DD);
    float4 v = xr[tid];

    __shared__ float red[8];
    float s = v.x + v.y + v.z + v.w;
    #pragma unroll
    for (int o = 16; o > 0; o >>= 1) s += __shfl_xor_sync(0xffffffffu, s, o);
    if ((tid & 31) == 0) red[tid >> 5] = s;
    __syncthreads();
    float tot = red[0]+red[1]+red[2]+red[3]+red[4]+red[5]+red[6]+red[7];
    float mean = tot * (1.0f / DD);

    float4 d;
    d.x = v.x - mean; d.y = v.y - mean; d.z = v.z - mean; d.w = v.w - mean;
    float s2 = d.x*d.x + d.y*d.y + d.z*d.z + d.w*d.w;
    #pragma unroll
    for (int o = 16; o > 0; o >>= 1) s2 += __shfl_xor_sync(0xffffffffu, s2, o);
    __syncthreads();
    if ((tid & 31) == 0) red[tid >> 5] = s2;
    __syncthreads();
    float var = (red[0]+red[1]+red[2]+red[3]+red[4]+red[5]+red[6]+red[7]) * (1.0f / DD);
    float rstd = rsqrtf(var + 1e-5f);

    float4 g  = ((const float4*)gamma)[tid];
    float4 bb = ((const float4*)beta)[tid];
    float4 o4;
    o4.x = d.x * rstd * g.x + bb.x;
    o4.y = d.y * rstd * g.y + bb.y;
    o4.z = d.z * rstd * g.z + bb.z;
    o4.w = d.w * rstd * g.w + bb.w;
    ((float4*)(g_xn + (size_t)row * DD))[tid] = o4;
}

// ---------------------------------------------------------------------------
// SGEMM: C[m,n] = sum_k A[m,k]*W[n,k] (+bias, + optional resid)
// 128x128 tile, BK=8, 256 threads, 8x8 per thread.
// srcSel: 0 -> A = g_xn, 1 -> A = g_ao
// dstSel: 0/1/2 -> g_q/g_k/g_v in [B,H,S,Hd] layout; 3 -> out[m*D+n] (+resid)
// ---------------------------------------------------------------------------
__global__ __launch_bounds__(256) void gemm_kernel(
    const float* __restrict__ W,
    const float* __restrict__ bias,
    const float* __restrict__ resid,
    float* __restrict__ out,
    int srcSel, int dstSel)
{
    __shared__ float As[8][128];
    __shared__ float Bs[8][128];

    const float* A = srcSel ? g_ao : g_xn;

    int tid = threadIdx.x;
    int m0 = blockIdx.y * 128;
    int n0 = blockIdx.x * 128;

    int lrow = tid >> 1;            // 0..127
    int lcol = (tid & 1) * 4;       // 0 or 4
    const float* Ag = A + (size_t)(m0 + lrow) * DD + lcol;
    const float* Wg = W + (size_t)(n0 + lrow) * DD + lcol;

    int tx = tid & 15;              // col tile 0..15
    int ty = tid >> 4;              // row tile 0..15

    float acc[8][8];
    #pragma unroll
    for (int i = 0; i < 8; i++)
        #pragma unroll
        for (int j = 0; j < 8; j++) acc[i][j] = 0.0f;

    for (int k0 = 0; k0 < DD; k0 += 8) {
        float4 av = *(const float4*)(Ag + k0);
        float4 bv = *(const float4*)(Wg + k0);
        As[lcol+0][lrow] = av.x; As[lcol+1][lrow] = av.y;
        As[lcol+2][lrow] = av.z; As[lcol+3][lrow] = av.w;
        Bs[lcol+0][lrow] = bv.x; Bs[lcol+1][lrow] = bv.y;
        Bs[lcol+2][lrow] = bv.z; Bs[lcol+3][lrow] = bv.w;
        __syncthreads();

        #pragma unroll
        for (int kk = 0; kk < 8; kk++) {
            float4 a0 = *(const float4*)(&As[kk][ty*8]);
            float4 a1 = *(const float4*)(&As[kk][ty*8+4]);
            float4 b0 = *(const float4*)(&Bs[kk][tx*8]);
            float4 b1 = *(const float4*)(&Bs[kk][tx*8+4]);
            float ra[8] = {a0.x,a0.y,a0.z,a0.w,a1.x,a1.y,a1.z,a1.w};
            float rb[8] = {b0.x,b0.y,b0.z,b0.w,b1.x,b1.y,b1.z,b1.w};
            #pragma unroll
            for (int i = 0; i < 8; i++)
                #pragma unroll
                for (int j = 0; j < 8; j++)
                    acc[i][j] = fmaf(ra[i], rb[j], acc[i][j]);
        }
        __syncthreads();
    }

    float* hdst = (dstSel == 0) ? g_q : (dstSel == 1) ? g_k : g_v;

    #pragma unroll
    for (int i = 0; i < 8; i++) {
        int m = m0 + ty*8 + i;
        #pragma unroll
        for (int j4 = 0; j4 < 8; j4 += 4) {
            int n = n0 + tx*8 + j4;
            float4 bz = *(const float4*)(bias + n);
            float4 r;
            r.x = acc[i][j4+0] + bz.x;
            r.y = acc[i][j4+1] + bz.y;
            r.z = acc[i][j4+2] + bz.z;
            r.w = acc[i][j4+3] + bz.w;
            if (dstSel < 3) {
                int h = n >> 6, hd = n & 63;
                int b = m >> 11, s = m & (SS - 1);
                size_t idx = ((size_t)(b*HH + h) * SS + s) * HDIM + hd;
                *(float4*)(hdst + idx) = r;
            } else {
                size_t idx = (size_t)m * DD + n;
                float4 rv = *(const float4*)(resid + idx);
                r.x += rv.x; r.y += rv.y; r.z += rv.z; r.w += rv.w;
                *(float4*)(out + idx) = r;
            }
        }
    }
}

// ---------------------------------------------------------------------------
// Causal flash attention. 64 queries x 64 keys per tile. Hd=64. 256 threads.
// Per-thread 4x4 micro-tile for both QK^T and PV. Q,K staged d-major (pad 68).
// grid: (S/64, B*H)
// ---------------------------------------------------------------------------
#define QPAD 68
#define PPAD 65
#define ATTN_SMEM_FLOATS (64*QPAD + 64*QPAD + 64*64 + 64*PPAD + 64)
#define ATTN_SMEM_BYTES  (ATTN_SMEM_FLOATS * 4)

__global__ __launch_bounds__(256) void attn_kernel(const float* __restrict__ mask)
{
    extern __shared__ float sm[];
    float* Qst = sm;                 // [64][QPAD]  Qst[d][r]
    float* Kst = Qst + 64*QPAD;      // [64][QPAD]  Kst[d][c]
    float* Vs  = Kst + 64*QPAD;      // [64][64]    Vs[c][d]
    float* Ps  = Vs  + 64*64;        // [64][PPAD]
    float* mv  = Ps  + 64*PPAD;      // [64]

    int qb = blockIdx.x;             // 0..31
    int bh = blockIdx.y;             // 0..63
    int b  = bh >> 4;
    int h  = bh & 15;

    const float* Qg  = g_q + ((size_t)bh * SS + qb*64) * HDIM;
    const float* Kg0 = g_k + (size_t)bh * SS * HDIM;
    const float* Vg0 = g_v + (size_t)bh * SS * HDIM;

    int tid = threadIdx.x;
    int tx = tid & 15;               // 0..15  -> cols tx*4..+3
    int ty = tid >> 4;               // 0..15  -> rows ty*4..+3

    // Load Q transposed
    {
        int r = tid >> 2, seg = tid & 3;
        const float4* qr = (const float4*)(Qg + r*HDIM + seg*16);
        #pragma unroll
        for (int i = 0; i < 4; i++) {
            float4 v = qr[i];
            int d = seg*16 + i*4;
            Qst[(d+0)*QPAD + r] = v.x;
            Qst[(d+1)*QPAD + r] = v.y;
            Qst[(d+2)*QPAD + r] = v.z;
            Qst[(d+3)*QPAD + r] = v.w;
        }
    }

    float mrow[4], lrow[4], o[4][4];
    #pragma unroll
    for (int i = 0; i < 4; i++) {
        mrow[i] = NEG_BIG; lrow[i] = 0.0f;
        #pragma unroll
        for (int j = 0; j < 4; j++) o[i][j] = 0.0f;
    }

    int rg0 = qb*64 + ty*4;

    for (int jb = 0; jb <= qb; jb++) {
        __syncthreads();   // prev PV done before K/V overwrite; covers Q load on jb==0
        {
            int c = tid >> 2, seg = tid & 3;
            const float4* kr = (const float4*)(Kg0 + (size_t)(jb*64 + c)*HDIM + seg*16);
            #pragma unroll
            for (int i = 0; i < 4; i++) {
                float4 v = kr[i];
                int d = seg*16 + i*4;
                Kst[(d+0)*QPAD + c] = v.x;
                Kst[(d+1)*QPAD + c] = v.y;
                Kst[(d+2)*QPAD + c] = v.z;
                Kst[(d+3)*QPAD + c] = v.w;
            }
            const float4* vr = (const float4*)(Vg0 + (size_t)(jb*64 + c)*HDIM + seg*16);
            float4* vd = (float4*)(Vs + c*64 + seg*16);
            #pragma unroll
            for (int i = 0; i < 4; i++) vd[i] = vr[i];
            if (tid < 64) mv[tid] = mask[b*SS + jb*64 + tid];
        }
        __syncthreads();

        // scores: s[i][j] = Q[rg0+i,:] . K[cg0+j,:]
        float s[4][4];
        #pragma unroll
        for (int i = 0; i < 4; i++)
            #pragma unroll
            for (int j = 0; j < 4; j++) s[i][j] = 0.0f;

        #pragma unroll 8
        for (int d = 0; d < 64; d++) {
            float4 qa = *(const float4*)(Qst + d*QPAD + ty*4);
            float4 kb = *(const float4*)(Kst + d*QPAD + tx*4);
            float ra[4] = {qa.x, qa.y, qa.z, qa.w};
            float rb[4] = {kb.x, kb.y, kb.z, kb.w};
            #pragma unroll
            for (int i = 0; i < 4; i++)
                #pragma unroll
                for (int j = 0; j < 4; j++)
                    s[i][j] = fmaf(ra[i], rb[j], s[i][j]);
        }

        int cg0 = jb*64 + tx*4;
        float pm[4];
        #pragma unroll
        for (int j = 0; j < 4; j++)
            pm[j] = -10000.0f * (1.0f - mv[tx*4 + j]);

        #pragma unroll
        for (int i = 0; i < 4; i++) {
            float rowmax = NEG_BIG;
            #pragma unroll
            for (int j = 0; j < 4; j++) {
                float val = s[i][j] * 0.125f + pm[j];
                if (cg0 + j > rg0 + i) val = NEG_BIG;   // causal
                s[i][j] = val;
                rowmax = fmaxf(rowmax, val);
            }
            #pragma unroll
            for (int off = 1; off < 16; off <<= 1)
                rowmax = fmaxf(rowmax, __shfl_xor_sync(0xffffffffu, rowmax, off));
            float mnew = fmaxf(mrow[i], rowmax);
            float sc = __expf(mrow[i] - mnew);
            mrow[i] = mnew;
            float ls = 0.0f;
            #pragma unroll
            for (int j = 0; j < 4; j++) {
                float p = __expf(s[i][j] - mnew);
                s[i][j] = p;
                ls += p;
            }
            #pragma unroll
            for (int off = 1; off < 16; off <<= 1)
                ls += __shfl_xor_sync(0xffffffffu, ls, off);
            lrow[i] = lrow[i] * sc + ls;
            #pragma unroll
            for (int j = 0; j < 4; j++) {
                o[i][j] *= sc;
                Ps[(ty*4 + i)*PPAD + tx*4 + j] = s[i][j];
            }
        }
        __syncthreads();

        // PV: o[i][j] += sum_c P[r,c] * V[c, d=tx*4+j]
        #pragma unroll 4
        for (int c = 0; c < 64; c++) {
            float4 vb = *(const float4*)(Vs + c*64 + tx*4);
            #pragma unroll
            for (int i = 0; i < 4; i++) {
                float p = Ps[(ty*4 + i)*PPAD + c];
                o[i][0] = fmaf(p, vb.x, o[i][0]);
                o[i][1] = fmaf(p, vb.y, o[i][1]);
                o[i][2] = fmaf(p, vb.z, o[i][2]);
                o[i][3] = fmaf(p, vb.w, o[i][3]);
            }
        }
    }

    // write to [B,S,D]
    #pragma unroll
    for (int i = 0; i < 4; i++) {
        float inv = 1.0f / lrow[i];
        size_t row = (size_t)b*SS + qb*64 + ty*4 + i;
        float4 r;
        r.x = o[i][0]*inv; r.y = o[i][1]*inv; r.z = o[i][2]*inv; r.w = o[i][3]*inv;
        *(float4*)(g_ao + row*DD + h*HDIM + tx*4) = r;
    }
}

// ---------------------------------------------------------------------------
extern "C" void kernel_launch(void* const* d_in, const int* in_sizes, int n_in,
                              void* d_out, int out_size)
{
    const float* x     = (const float*)d_in[0];
    const float* amask = (const float*)d_in[1];
    const float* Wq    = (const float*)d_in[2];
    const float* bq    = (const float*)d_in[3];
    const float* Wk    = (const float*)d_in[4];
    const float* bk    = (const float*)d_in[5];
    const float* Wv    = (const float*)d_in[6];
    const float* bv    = (const float*)d_in[7];
    const float* Wo    = (const float*)d_in[8];
    const float* bo    = (const float*)d_in[9];
    const float* gam   = (const float*)d_in[10];
    const float* bet   = (const float*)d_in[11];
    float* out = (float*)d_out;

    cudaFuncSetAttribute(attn_kernel,
                         cudaFuncAttributeMaxDynamicSharedMemorySize,
                         ATTN_SMEM_BYTES);

    ln_kernel<<<MM, 256>>>(x, gam, bet);

    dim3 ggrid(DD/128, MM/128);   // (8, 64)
    gemm_kernel<<<ggrid, 256>>>(Wq, bq, nullptr, nullptr, 0, 0);
    gemm_kernel<<<ggrid, 256>>>(Wk, bk, nullptr, nullptr, 0, 1);
    gemm_kernel<<<ggrid, 256>>>(Wv, bv, nullptr, nullptr, 0, 2);

    dim3 agrid(SS/64, BB*HH);     // (32, 64)
    attn_kernel<<<agrid, 256, ATTN_SMEM_BYTES>>>(amask);

    gemm_kernel<<<ggrid, 256>>>(Wo, bo, x, out, 1, 3);
}

// round 3
// speedup vs baseline: 1.7080x; 1.7080x over previous
#include <cuda_runtime.h>
#include <cuda_bf16.h>
#include <cstdint>
#include <math.h>

// Problem constants (fixed by reference setup_inputs)
#define BB   4
#define SS   2048
#define DD   1024
#define HH   16
#define HDIM 64
#define MM   (BB*SS)          // 8192

#define NEG_BIG (-1e30f)

// Scratch (device globals: allocation-free rule)
__device__ float g_xn[MM*DD];
__device__ float g_q [MM*DD];   // [B,H,S,Hd]
__device__ float g_k [MM*DD];
__device__ float g_v [MM*DD];
__device__ float g_ao[MM*DD];   // [B,S,D]

__device__ __forceinline__ uint32_t f2tf32(float f) {
    uint32_t u;
    asm("cvt.rna.tf32.f32 %0, %1;" : "=r"(u) : "f"(f));
    return u;
}

__device__ __forceinline__ void mma_tf32(float& c0, float& c1, float& c2, float& c3,
                                         uint32_t a0, uint32_t a1, uint32_t a2, uint32_t a3,
                                         uint32_t b0, uint32_t b1) {
    asm volatile(
        "mma.sync.aligned.m16n8k8.row.col.f32.tf32.tf32.f32 "
        "{%0,%1,%2,%3}, {%4,%5,%6,%7}, {%8,%9}, {%0,%1,%2,%3};"
        : "+f"(c0), "+f"(c1), "+f"(c2), "+f"(c3)
        : "r"(a0), "r"(a1), "r"(a2), "r"(a3), "r"(b0), "r"(b1));
}

// ---------------------------------------------------------------------------
// LayerNorm: one block per row, 256 threads, float4
// ---------------------------------------------------------------------------
__global__ __launch_bounds__(256) void ln_kernel(
    const float* __restrict__ x,
    const float* __restrict__ gamma,
    const float* __restrict__ beta)
{
    int row = blockIdx.x;
    int tid = threadIdx.x;
    const float4* xr = (const float4*)(x + (size_t)row * DD);
    float4 v = xr[tid];

    __shared__ float red[8];
    float s = v.x + v.y + v.z + v.w;
    #pragma unroll
    for (int o = 16; o > 0; o >>= 1) s += __shfl_xor_sync(0xffffffffu, s, o);
    if ((tid & 31) == 0) red[tid >> 5] = s;
    __syncthreads();
    float tot = red[0]+red[1]+red[2]+red[3]+red[4]+red[5]+red[6]+red[7];
    float mean = tot * (1.0f / DD);

    float4 d;
    d.x = v.x - mean; d.y = v.y - mean; d.z = v.z - mean; d.w = v.w - mean;
    float s2 = d.x*d.x + d.y*d.y + d.z*d.z + d.w*d.w;
    #pragma unroll
    for (int o = 16; o > 0; o >>= 1) s2 += __shfl_xor_sync(0xffffffffu, s2, o);
    __syncthreads();
    if ((tid & 31) == 0) red[tid >> 5] = s2;
    __syncthreads();
    float var = (red[0]+red[1]+red[2]+red[3]+red[4]+red[5]+red[6]+red[7]) * (1.0f / DD);
    float rstd = rsqrtf(var + 1e-5f);

    float4 g  = ((const float4*)gamma)[tid];
    float4 bb = ((const float4*)beta)[tid];
    float4 o4;
    o4.x = d.x * rstd * g.x + bb.x;
    o4.y = d.y * rstd * g.y + bb.y;
    o4.z = d.z * rstd * g.z + bb.z;
    o4.w = d.w * rstd * g.w + bb.w;
    ((float4*)(g_xn + (size_t)row * DD))[tid] = o4;
}

// ---------------------------------------------------------------------------
// Tensor-core (mma.sync tf32) GEMM: C[m,n] = sum_k A[m,k]*W[n,k] (+bias/resid)
// 128x128 tile, BK=32, 256 threads (8 warps, 4m x 2n), warp tile 32x64.
// srcSel: 0 -> A = g_xn, 1 -> A = g_ao
// dstSel: 0/1/2 -> g_q/g_k/g_v in [B,H,S,Hd] layout; 3 -> out[m*D+n] (+resid)
// ---------------------------------------------------------------------------
#define KPAD 36

__global__ __launch_bounds__(256) void gemm_mma(
    const float* __restrict__ W,
    const float* __restrict__ bias,
    const float* __restrict__ resid,
    float* __restrict__ out,
    int srcSel, int dstSel)
{
    __shared__ uint32_t As[128 * KPAD];   // As[m][k] tf32 bits
    __shared__ uint32_t Bs[128 * KPAD];   // Bs[n][k] tf32 bits

    const float* A = srcSel ? g_ao : g_xn;

    int tid = threadIdx.x;
    int wid = tid >> 5, lane = tid & 31;
    int m0 = blockIdx.y * 128;
    int n0 = blockIdx.x * 128;

    int wm = (wid & 3) * 32;     // warp m offset in tile
    int wn = (wid >> 2) * 64;    // warp n offset in tile

    int lr = lane >> 2;          // 0..7
    int lc = lane & 3;           // 0..3

    // staging indices: 4 float4 per thread per tile
    int srow[4], sc4[4];
    #pragma unroll
    for (int i = 0; i < 4; i++) {
        int f4 = tid + i * 256;          // 0..1023
        srow[i] = f4 >> 3;               // 0..127
        sc4[i]  = f4 & 7;                // float4 idx within 32-wide k row
    }

    float acc[2][8][4];
    #pragma unroll
    for (int tm = 0; tm < 2; tm++)
        #pragma unroll
        for (int tn = 0; tn < 8; tn++)
            #pragma unroll
            for (int c = 0; c < 4; c++) acc[tm][tn][c] = 0.0f;

    // prefetch tile 0
    float4 ra[4], rb[4];
    #pragma unroll
    for (int i = 0; i < 4; i++) {
        ra[i] = *(const float4*)(A + (size_t)(m0 + srow[i]) * DD + sc4[i] * 4);
        rb[i] = *(const float4*)(W + (size_t)(n0 + srow[i]) * DD + sc4[i] * 4);
    }

    for (int kt = 0; kt < 32; kt++) {
        // store staged regs (converted to tf32) into smem
        #pragma unroll
        for (int i = 0; i < 4; i++) {
            uint4 at, wt;
            at.x = f2tf32(ra[i].x); at.y = f2tf32(ra[i].y);
            at.z = f2tf32(ra[i].z); at.w = f2tf32(ra[i].w);
            wt.x = f2tf32(rb[i].x); wt.y = f2tf32(rb[i].y);
            wt.z = f2tf32(rb[i].z); wt.w = f2tf32(rb[i].w);
            *(uint4*)(&As[srow[i] * KPAD + sc4[i] * 4]) = at;
            *(uint4*)(&Bs[srow[i] * KPAD + sc4[i] * 4]) = wt;
        }
        __syncthreads();

        // prefetch next tile into regs
        if (kt < 31) {
            int k0n = (kt + 1) * 32;
            #pragma unroll
            for (int i = 0; i < 4; i++) {
                ra[i] = *(const float4*)(A + (size_t)(m0 + srow[i]) * DD + k0n + sc4[i] * 4);
                rb[i] = *(const float4*)(W + (size_t)(n0 + srow[i]) * DD + k0n + sc4[i] * 4);
            }
        }

        // compute 4 k-steps of 8
        #pragma unroll
        for (int ks = 0; ks < 4; ks++) {
            int k0 = ks * 8;
            uint32_t af[2][4];
            #pragma unroll
            for (int tm = 0; tm < 2; tm++) {
                int base = (wm + tm * 16 + lr) * KPAD + k0 + lc;
                af[tm][0] = As[base];
                af[tm][1] = As[base + 8 * KPAD];
                af[tm][2] = As[base + 4];
                af[tm][3] = As[base + 8 * KPAD + 4];
            }
            uint32_t bf[8][2];
            #pragma unroll
            for (int tn = 0; tn < 8; tn++) {
                int base = (wn + tn * 8 + lr) * KPAD + k0 + lc;
                bf[tn][0] = Bs[base];
                bf[tn][1] = Bs[base + 4];
            }
            #pragma unroll
            for (int tm = 0; tm < 2; tm++)
                #pragma unroll
                for (int tn = 0; tn < 8; tn++)
                    mma_tf32(acc[tm][tn][0], acc[tm][tn][1], acc[tm][tn][2], acc[tm][tn][3],
                             af[tm][0], af[tm][1], af[tm][2], af[tm][3],
                             bf[tn][0], bf[tn][1]);
        }
        __syncthreads();
    }

    // epilogue
    float* hdst = (dstSel == 0) ? g_q : (dstSel == 1) ? g_k : g_v;
    #pragma unroll
    for (int tm = 0; tm < 2; tm++) {
        #pragma unroll
        for (int half = 0; half < 2; half++) {
            int m = m0 + wm + tm * 16 + lr + half * 8;
            int bI = m >> 11, sI = m & (SS - 1);
            #pragma unroll
            for (int tn = 0; tn < 8; tn++) {
                int n = n0 + wn + tn * 8 + lc * 2;
                float2 bz = *(const float2*)(bias + n);
                float2 r;
                r.x = acc[tm][tn][half*2+0] + bz.x;
                r.y = acc[tm][tn][half*2+1] + bz.y;
                if (dstSel < 3) {
                    int h = n >> 6, hd = n & 63;
                    size_t idx = ((size_t)(bI * HH + h) * SS + sI) * HDIM + hd;
                    *(float2*)(hdst + idx) = r;
                } else {
                    size_t idx = (size_t)m * DD + n;
                    float2 rv = *(const float2*)(resid + idx);
                    r.x += rv.x; r.y += rv.y;
                    *(float2*)(out + idx) = r;
                }
            }
        }
    }
}

// ---------------------------------------------------------------------------
// Causal flash attention. 64 queries x 64 keys per tile. Hd=64. 256 threads.
// ---------------------------------------------------------------------------
#define QPAD 68
#define PPAD 65
#define ATTN_SMEM_FLOATS (64*QPAD + 64*QPAD + 64*64 + 64*PPAD + 64)
#define ATTN_SMEM_BYTES  (ATTN_SMEM_FLOATS * 4)

__global__ __launch_bounds__(256) void attn_kernel(const float* __restrict__ mask)
{
    extern __shared__ float sm[];
    float* Qst = sm;                 // [64][QPAD]  Qst[d][r]
    float* Kst = Qst + 64*QPAD;      // [64][QPAD]  Kst[d][c]
    float* Vs  = Kst + 64*QPAD;      // [64][64]    Vs[c][d]
    float* Ps  = Vs  + 64*64;        // [64][PPAD]
    float* mv  = Ps  + 64*PPAD;      // [64]

    int qb = blockIdx.x;             // 0..31
    int bh = blockIdx.y;             // 0..63
    int b  = bh >> 4;
    int h  = bh & 15;

    const float* Qg  = g_q + ((size_t)bh * SS + qb*64) * HDIM;
    const float* Kg0 = g_k + (size_t)bh * SS * HDIM;
    const float* Vg0 = g_v + (size_t)bh * SS * HDIM;

    int tid = threadIdx.x;
    int tx = tid & 15;
    int ty = tid >> 4;

    {
        int r = tid >> 2, seg = tid & 3;
        const float4* qr = (const float4*)(Qg + r*HDIM + seg*16);
        #pragma unroll
        for (int i = 0; i < 4; i++) {
            float4 v = qr[i];
            int d = seg*16 + i*4;
            Qst[(d+0)*QPAD + r] = v.x;
            Qst[(d+1)*QPAD + r] = v.y;
            Qst[(d+2)*QPAD + r] = v.z;
            Qst[(d+3)*QPAD + r] = v.w;
        }
    }

    float mrow[4], lrow[4], o[4][4];
    #pragma unroll
    for (int i = 0; i < 4; i++) {
        mrow[i] = NEG_BIG; lrow[i] = 0.0f;
        #pragma unroll
        for (int j = 0; j < 4; j++) o[i][j] = 0.0f;
    }

    int rg0 = qb*64 + ty*4;

    for (int jb = 0; jb <= qb; jb++) {
        __syncthreads();
        {
            int c = tid >> 2, seg = tid & 3;
            const float4* kr = (const float4*)(Kg0 + (size_t)(jb*64 + c)*HDIM + seg*16);
            #pragma unroll
            for (int i = 0; i < 4; i++) {
                float4 v = kr[i];
                int d = seg*16 + i*4;
                Kst[(d+0)*QPAD + c] = v.x;
                Kst[(d+1)*QPAD + c] = v.y;
                Kst[(d+2)*QPAD + c] = v.z;
                Kst[(d+3)*QPAD + c] = v.w;
            }
            const float4* vr = (const float4*)(Vg0 + (size_t)(jb*64 + c)*HDIM + seg*16);
            float4* vd = (float4*)(Vs + c*64 + seg*16);
            #pragma unroll
            for (int i = 0; i < 4; i++) vd[i] = vr[i];
            if (tid < 64) mv[tid] = mask[b*SS + jb*64 + tid];
        }
        __syncthreads();

        float s[4][4];
        #pragma unroll
        for (int i = 0; i < 4; i++)
            #pragma unroll
            for (int j = 0; j < 4; j++) s[i][j] = 0.0f;

        #pragma unroll 8
        for (int d = 0; d < 64; d++) {
            float4 qa = *(const float4*)(Qst + d*QPAD + ty*4);
            float4 kb = *(const float4*)(Kst + d*QPAD + tx*4);
            float raa[4] = {qa.x, qa.y, qa.z, qa.w};
            float rbb[4] = {kb.x, kb.y, kb.z, kb.w};
            #pragma unroll
            for (int i = 0; i < 4; i++)
                #pragma unroll
                for (int j = 0; j < 4; j++)
                    s[i][j] = fmaf(raa[i], rbb[j], s[i][j]);
        }

        int cg0 = jb*64 + tx*4;
        float pm[4];
        #pragma unroll
        for (int j = 0; j < 4; j++)
            pm[j] = -10000.0f * (1.0f - mv[tx*4 + j]);

        #pragma unroll
        for (int i = 0; i < 4; i++) {
            float rowmax = NEG_BIG;
            #pragma unroll
            for (int j = 0; j < 4; j++) {
                float val = s[i][j] * 0.125f + pm[j];
                if (cg0 + j > rg0 + i) val = NEG_BIG;
                s[i][j] = val;
                rowmax = fmaxf(rowmax, val);
            }
            #pragma unroll
            for (int off = 1; off < 16; off <<= 1)
                rowmax = fmaxf(rowmax, __shfl_xor_sync(0xffffffffu, rowmax, off));
            float mnew = fmaxf(mrow[i], rowmax);
            float sc = __expf(mrow[i] - mnew);
            mrow[i] = mnew;
            float ls = 0.0f;
            #pragma unroll
            for (int j = 0; j < 4; j++) {
                float p = __expf(s[i][j] - mnew);
                s[i][j] = p;
                ls += p;
            }
            #pragma unroll
            for (int off = 1; off < 16; off <<= 1)
                ls += __shfl_xor_sync(0xffffffffu, ls, off);
            lrow[i] = lrow[i] * sc + ls;
            #pragma unroll
            for (int j = 0; j < 4; j++) {
                o[i][j] *= sc;
                Ps[(ty*4 + i)*PPAD + tx*4 + j] = s[i][j];
            }
        }
        __syncthreads();

        #pragma unroll 4
        for (int c = 0; c < 64; c++) {
            float4 vb = *(const float4*)(Vs + c*64 + tx*4);
            #pragma unroll
            for (int i = 0; i < 4; i++) {
                float p = Ps[(ty*4 + i)*PPAD + c];
                o[i][0] = fmaf(p, vb.x, o[i][0]);
                o[i][1] = fmaf(p, vb.y, o[i][1]);
                o[i][2] = fmaf(p, vb.z, o[i][2]);
                o[i][3] = fmaf(p, vb.w, o[i][3]);
            }
        }
    }

    #pragma unroll
    for (int i = 0; i < 4; i++) {
        float inv = 1.0f / lrow[i];
        size_t row = (size_t)b*SS + qb*64 + ty*4 + i;
        float4 r;
        r.x = o[i][0]*inv; r.y = o[i][1]*inv; r.z = o[i][2]*inv; r.w = o[i][3]*inv;
        *(float4*)(g_ao + row*DD + h*HDIM + tx*4) = r;
    }
}

// ---------------------------------------------------------------------------
extern "C" void kernel_launch(void* const* d_in, const int* in_sizes, int n_in,
                              void* d_out, int out_size)
{
    const float* x     = (const float*)d_in[0];
    const float* amask = (const float*)d_in[1];
    const float* Wq    = (const float*)d_in[2];
    const float* bq    = (const float*)d_in[3];
    const float* Wk    = (const float*)d_in[4];
    const float* bk    = (const float*)d_in[5];
    const float* Wv    = (const float*)d_in[6];
    const float* bv    = (const float*)d_in[7];
    const float* Wo    = (const float*)d_in[8];
    const float* bo    = (const float*)d_in[9];
    const float* gam   = (const float*)d_in[10];
    const float* bet   = (const float*)d_in[11];
    float* out = (float*)d_out;

    cudaFuncSetAttribute(attn_kernel,
                         cudaFuncAttributeMaxDynamicSharedMemorySize,
                         ATTN_SMEM_BYTES);

    ln_kernel<<<MM, 256>>>(x, gam, bet);

    dim3 ggrid(DD/128, MM/128);   // (8, 64)
    gemm_mma<<<ggrid, 256>>>(Wq, bq, nullptr, nullptr, 0, 0);
    gemm_mma<<<ggrid, 256>>>(Wk, bk, nullptr, nullptr, 0, 1);
    gemm_mma<<<ggrid, 256>>>(Wv, bv, nullptr, nullptr, 0, 2);

    dim3 agrid(SS/64, BB*HH);     // (32, 64)
    attn_kernel<<<agrid, 256, ATTN_SMEM_BYTES>>>(amask);

    gemm_mma<<<ggrid, 256>>>(Wo, bo, x, out, 1, 3);
}

// round 4
// speedup vs baseline: 3.0108x; 1.7627x over previous
#include <cuda_runtime.h>
#include <cuda_bf16.h>
#include <cstdint>
#include <math.h>

// Problem constants (fixed by reference setup_inputs)
#define BB   4
#define SS   2048
#define DD   1024
#define HH   16
#define HDIM 64
#define MM   (BB*SS)          // 8192

#define NEG_BIG (-1e30f)

// Scratch (device globals: allocation-free rule)
__device__ float g_xn[MM*DD];
__device__ float g_q [MM*DD];   // [B,H,S,Hd]
__device__ float g_k [MM*DD];
__device__ float g_v [MM*DD];
__device__ float g_ao[MM*DD];   // [B,S,D]

__device__ __forceinline__ uint32_t f2tf32(float f) {
    uint32_t u;
    asm("cvt.rna.tf32.f32 %0, %1;" : "=r"(u) : "f"(f));
    return u;
}

__device__ __forceinline__ void mma_tf32(float& c0, float& c1, float& c2, float& c3,
                                         uint32_t a0, uint32_t a1, uint32_t a2, uint32_t a3,
                                         uint32_t b0, uint32_t b1) {
    asm volatile(
        "mma.sync.aligned.m16n8k8.row.col.f32.tf32.tf32.f32 "
        "{%0,%1,%2,%3}, {%4,%5,%6,%7}, {%8,%9}, {%0,%1,%2,%3};"
        : "+f"(c0), "+f"(c1), "+f"(c2), "+f"(c3)
        : "r"(a0), "r"(a1), "r"(a2), "r"(a3), "r"(b0), "r"(b1));
}

// ---------------------------------------------------------------------------
// LayerNorm: one block per row, 256 threads, float4
// ---------------------------------------------------------------------------
__global__ __launch_bounds__(256) void ln_kernel(
    const float* __restrict__ x,
    const float* __restrict__ gamma,
    const float* __restrict__ beta)
{
    int row = blockIdx.x;
    int tid = threadIdx.x;
    const float4* xr = (const float4*)(x + (size_t)row * DD);
    float4 v = xr[tid];

    __shared__ float red[8];
    float s = v.x + v.y + v.z + v.w;
    #pragma unroll
    for (int o = 16; o > 0; o >>= 1) s += __shfl_xor_sync(0xffffffffu, s, o);
    if ((tid & 31) == 0) red[tid >> 5] = s;
    __syncthreads();
    float tot = red[0]+red[1]+red[2]+red[3]+red[4]+red[5]+red[6]+red[7];
    float mean = tot * (1.0f / DD);

    float4 d;
    d.x = v.x - mean; d.y = v.y - mean; d.z = v.z - mean; d.w = v.w - mean;
    float s2 = d.x*d.x + d.y*d.y + d.z*d.z + d.w*d.w;
    #pragma unroll
    for (int o = 16; o > 0; o >>= 1) s2 += __shfl_xor_sync(0xffffffffu, s2, o);
    __syncthreads();
    if ((tid & 31) == 0) red[tid >> 5] = s2;
    __syncthreads();
    float var = (red[0]+red[1]+red[2]+red[3]+red[4]+red[5]+red[6]+red[7]) * (1.0f / DD);
    float rstd = rsqrtf(var + 1e-5f);

    float4 g  = ((const float4*)gamma)[tid];
    float4 bb = ((const float4*)beta)[tid];
    float4 o4;
    o4.x = d.x * rstd * g.x + bb.x;
    o4.y = d.y * rstd * g.y + bb.y;
    o4.z = d.z * rstd * g.z + bb.z;
    o4.w = d.w * rstd * g.w + bb.w;
    ((float4*)(g_xn + (size_t)row * DD))[tid] = o4;
}

// ---------------------------------------------------------------------------
// Tensor-core (mma.sync tf32) GEMM: C[m,n] = sum_k A[m,k]*W[n,k] (+bias/resid)
// 128x128 tile, BK=32, 256 threads (8 warps, 4m x 2n), warp tile 32x64.
// ---------------------------------------------------------------------------
#define KPAD 36

__global__ __launch_bounds__(256) void gemm_mma(
    const float* __restrict__ W,
    const float* __restrict__ bias,
    const float* __restrict__ resid,
    float* __restrict__ out,
    int srcSel, int dstSel)
{
    __shared__ uint32_t As[128 * KPAD];
    __shared__ uint32_t Bs[128 * KPAD];

    const float* A = srcSel ? g_ao : g_xn;

    int tid = threadIdx.x;
    int wid = tid >> 5, lane = tid & 31;
    int m0 = blockIdx.y * 128;
    int n0 = blockIdx.x * 128;

    int wm = (wid & 3) * 32;
    int wn = (wid >> 2) * 64;

    int lr = lane >> 2;
    int lc = lane & 3;

    int srow[4], sc4[4];
    #pragma unroll
    for (int i = 0; i < 4; i++) {
        int f4 = tid + i * 256;
        srow[i] = f4 >> 3;
        sc4[i]  = f4 & 7;
    }

    float acc[2][8][4];
    #pragma unroll
    for (int tm = 0; tm < 2; tm++)
        #pragma unroll
        for (int tn = 0; tn < 8; tn++)
            #pragma unroll
            for (int c = 0; c < 4; c++) acc[tm][tn][c] = 0.0f;

    float4 ra[4], rb[4];
    #pragma unroll
    for (int i = 0; i < 4; i++) {
        ra[i] = *(const float4*)(A + (size_t)(m0 + srow[i]) * DD + sc4[i] * 4);
        rb[i] = *(const float4*)(W + (size_t)(n0 + srow[i]) * DD + sc4[i] * 4);
    }

    for (int kt = 0; kt < 32; kt++) {
        #pragma unroll
        for (int i = 0; i < 4; i++) {
            uint4 at, wt;
            at.x = f2tf32(ra[i].x); at.y = f2tf32(ra[i].y);
            at.z = f2tf32(ra[i].z); at.w = f2tf32(ra[i].w);
            wt.x = f2tf32(rb[i].x); wt.y = f2tf32(rb[i].y);
            wt.z = f2tf32(rb[i].z); wt.w = f2tf32(rb[i].w);
            *(uint4*)(&As[srow[i] * KPAD + sc4[i] * 4]) = at;
            *(uint4*)(&Bs[srow[i] * KPAD + sc4[i] * 4]) = wt;
        }
        __syncthreads();

        if (kt < 31) {
            int k0n = (kt + 1) * 32;
            #pragma unroll
            for (int i = 0; i < 4; i++) {
                ra[i] = *(const float4*)(A + (size_t)(m0 + srow[i]) * DD + k0n + sc4[i] * 4);
                rb[i] = *(const float4*)(W + (size_t)(n0 + srow[i]) * DD + k0n + sc4[i] * 4);
            }
        }

        #pragma unroll
        for (int ks = 0; ks < 4; ks++) {
            int k0 = ks * 8;
            uint32_t af[2][4];
            #pragma unroll
            for (int tm = 0; tm < 2; tm++) {
                int base = (wm + tm * 16 + lr) * KPAD + k0 + lc;
                af[tm][0] = As[base];
                af[tm][1] = As[base + 8 * KPAD];
                af[tm][2] = As[base + 4];
                af[tm][3] = As[base + 8 * KPAD + 4];
            }
            uint32_t bf[8][2];
            #pragma unroll
            for (int tn = 0; tn < 8; tn++) {
                int base = (wn + tn * 8 + lr) * KPAD + k0 + lc;
                bf[tn][0] = Bs[base];
                bf[tn][1] = Bs[base + 4];
            }
            #pragma unroll
            for (int tm = 0; tm < 2; tm++)
                #pragma unroll
                for (int tn = 0; tn < 8; tn++)
                    mma_tf32(acc[tm][tn][0], acc[tm][tn][1], acc[tm][tn][2], acc[tm][tn][3],
                             af[tm][0], af[tm][1], af[tm][2], af[tm][3],
                             bf[tn][0], bf[tn][1]);
        }
        __syncthreads();
    }

    float* hdst = (dstSel == 0) ? g_q : (dstSel == 1) ? g_k : g_v;
    #pragma unroll
    for (int tm = 0; tm < 2; tm++) {
        #pragma unroll
        for (int half = 0; half < 2; half++) {
            int m = m0 + wm + tm * 16 + lr + half * 8;
            int bI = m >> 11, sI = m & (SS - 1);
            #pragma unroll
            for (int tn = 0; tn < 8; tn++) {
                int n = n0 + wn + tn * 8 + lc * 2;
                float2 bz = *(const float2*)(bias + n);
                float2 r;
                r.x = acc[tm][tn][half*2+0] + bz.x;
                r.y = acc[tm][tn][half*2+1] + bz.y;
                if (dstSel < 3) {
                    int h = n >> 6, hd = n & 63;
                    size_t idx = ((size_t)(bI * HH + h) * SS + sI) * HDIM + hd;
                    *(float2*)(hdst + idx) = r;
                } else {
                    size_t idx = (size_t)m * DD + n;
                    float2 rv = *(const float2*)(resid + idx);
                    r.x += rv.x; r.y += rv.y;
                    *(float2*)(out + idx) = r;
                }
            }
        }
    }
}

// ---------------------------------------------------------------------------
// Tensor-core causal flash attention.
// 128 queries x 64 keys per iteration, Hd=64, 8 warps (warp = 16 full rows).
// QK^T and PV both on mma.sync tf32. Online softmax in C-fragment layout.
// grid: (S/128 = 16, B*H = 64)
// ---------------------------------------------------------------------------
#define DPAD 68
#define ATTN2_SMEM_WORDS (128*DPAD + 64*DPAD + 64*DPAD + 128*DPAD + 64)
#define ATTN2_SMEM_BYTES (ATTN2_SMEM_WORDS * 4)

__global__ __launch_bounds__(256) void attn_mma(const float* __restrict__ mask)
{
    extern __shared__ uint32_t sm2[];
    uint32_t* Qs = sm2;                   // [128][DPAD] tf32
    uint32_t* Ks = Qs + 128*DPAD;         // [64][DPAD]  tf32 K[key][d]
    uint32_t* Vs = Ks + 64*DPAD;          // [64][DPAD]  tf32 V[key][d]
    uint32_t* Ps = Vs + 64*DPAD;          // [128][DPAD] tf32 P
    float*    mv = (float*)(Ps + 128*DPAD);  // [64]

    int qb = (int)gridDim.x - 1 - (int)blockIdx.x;   // heavy blocks first
    int bh = blockIdx.y;
    int b = bh >> 4, h = bh & 15;

    const float* Qg = g_q + ((size_t)bh * SS + qb * 128) * HDIM;
    const float* Kg = g_k + (size_t)bh * SS * HDIM;
    const float* Vg = g_v + (size_t)bh * SS * HDIM;

    int tid = threadIdx.x;
    int wid = tid >> 5, lane = tid & 31;
    int lr = lane >> 2, lc = lane & 3;
    int wm = wid * 16;

    // stage Q (tf32)
    #pragma unroll
    for (int i = 0; i < 8; i++) {
        int f4 = tid + i * 256;
        int row = f4 >> 4, c4 = f4 & 15;
        float4 v = *(const float4*)(Qg + row * HDIM + c4 * 4);
        uint4 t;
        t.x = f2tf32(v.x); t.y = f2tf32(v.y); t.z = f2tf32(v.z); t.w = f2tf32(v.w);
        *(uint4*)(Qs + row * DPAD + c4 * 4) = t;
    }

    float of[8][4];
    #pragma unroll
    for (int nt = 0; nt < 8; nt++)
        #pragma unroll
        for (int c = 0; c < 4; c++) of[nt][c] = 0.0f;
    float m0 = NEG_BIG, m1 = NEG_BIG, l0 = 0.0f, l1 = 0.0f;

    int row_g0 = qb * 128 + wm + lr;
    int row_g1 = row_g0 + 8;

    int arow0 = (wm + lr) * DPAD;
    int arow1 = (wm + lr + 8) * DPAD;

    int jbmax = 2 * qb + 1;
    for (int jb = 0; jb <= jbmax; jb++) {
        __syncthreads();
        #pragma unroll
        for (int i = 0; i < 4; i++) {
            int f4 = tid + i * 256;
            int row = f4 >> 4, c4 = f4 & 15;
            float4 kv = *(const float4*)(Kg + (size_t)(jb * 64 + row) * HDIM + c4 * 4);
            float4 vv = *(const float4*)(Vg + (size_t)(jb * 64 + row) * HDIM + c4 * 4);
            uint4 kt, vt;
            kt.x = f2tf32(kv.x); kt.y = f2tf32(kv.y); kt.z = f2tf32(kv.z); kt.w = f2tf32(kv.w);
            vt.x = f2tf32(vv.x); vt.y = f2tf32(vv.y); vt.z = f2tf32(vv.z); vt.w = f2tf32(vv.w);
            *(uint4*)(Ks + row * DPAD + c4 * 4) = kt;
            *(uint4*)(Vs + row * DPAD + c4 * 4) = vt;
        }
        if (tid < 64) mv[tid] = mask[b * SS + jb * 64 + tid];
        __syncthreads();

        // S = Q K^T  (warp: 16 rows x 64 cols)
        float sf[8][4];
        #pragma unroll
        for (int nt = 0; nt < 8; nt++)
            #pragma unroll
            for (int c = 0; c < 4; c++) sf[nt][c] = 0.0f;

        #pragma unroll
        for (int ks = 0; ks < 8; ks++) {
            int k0 = ks * 8;
            uint32_t a0 = Qs[arow0 + k0 + lc];
            uint32_t a1 = Qs[arow1 + k0 + lc];
            uint32_t a2 = Qs[arow0 + k0 + lc + 4];
            uint32_t a3 = Qs[arow1 + k0 + lc + 4];
            #pragma unroll
            for (int nt = 0; nt < 8; nt++) {
                uint32_t b0 = Ks[(nt * 8 + lr) * DPAD + k0 + lc];
                uint32_t b1 = Ks[(nt * 8 + lr) * DPAD + k0 + lc + 4];
                mma_tf32(sf[nt][0], sf[nt][1], sf[nt][2], sf[nt][3],
                         a0, a1, a2, a3, b0, b1);
            }
        }

        // masks + row max
        float rmax0 = NEG_BIG, rmax1 = NEG_BIG;
        #pragma unroll
        for (int nt = 0; nt < 8; nt++) {
            int cg = jb * 64 + nt * 8 + lc * 2;
            float pma = -10000.0f * (1.0f - mv[nt * 8 + lc * 2]);
            float pmb = -10000.0f * (1.0f - mv[nt * 8 + lc * 2 + 1]);
            float v0 = sf[nt][0] * 0.125f + pma; if (cg     > row_g0) v0 = NEG_BIG;
            float v1 = sf[nt][1] * 0.125f + pmb; if (cg + 1 > row_g0) v1 = NEG_BIG;
            float v2 = sf[nt][2] * 0.125f + pma; if (cg     > row_g1) v2 = NEG_BIG;
            float v3 = sf[nt][3] * 0.125f + pmb; if (cg + 1 > row_g1) v3 = NEG_BIG;
            sf[nt][0] = v0; sf[nt][1] = v1; sf[nt][2] = v2; sf[nt][3] = v3;
            rmax0 = fmaxf(rmax0, fmaxf(v0, v1));
            rmax1 = fmaxf(rmax1, fmaxf(v2, v3));
        }
        rmax0 = fmaxf(rmax0, __shfl_xor_sync(0xffffffffu, rmax0, 1));
        rmax0 = fmaxf(rmax0, __shfl_xor_sync(0xffffffffu, rmax0, 2));
        rmax1 = fmaxf(rmax1, __shfl_xor_sync(0xffffffffu, rmax1, 1));
        rmax1 = fmaxf(rmax1, __shfl_xor_sync(0xffffffffu, rmax1, 2));

        float mn0 = fmaxf(m0, rmax0), mn1 = fmaxf(m1, rmax1);
        float sc0 = __expf(m0 - mn0), sc1 = __expf(m1 - mn1);
        m0 = mn0; m1 = mn1;

        float ls0 = 0.0f, ls1 = 0.0f;
        #pragma unroll
        for (int nt = 0; nt < 8; nt++) {
            float p0 = __expf(sf[nt][0] - mn0);
            float p1 = __expf(sf[nt][1] - mn0);
            float p2 = __expf(sf[nt][2] - mn1);
            float p3 = __expf(sf[nt][3] - mn1);
            ls0 += p0 + p1; ls1 += p2 + p3;
            uint2 w0; w0.x = f2tf32(p0); w0.y = f2tf32(p1);
            uint2 w1; w1.x = f2tf32(p2); w1.y = f2tf32(p3);
            *(uint2*)(Ps + arow0 + nt * 8 + lc * 2) = w0;
            *(uint2*)(Ps + arow1 + nt * 8 + lc * 2) = w1;
            of[nt][0] *= sc0; of[nt][1] *= sc0;
            of[nt][2] *= sc1; of[nt][3] *= sc1;
        }
        ls0 += __shfl_xor_sync(0xffffffffu, ls0, 1);
        ls0 += __shfl_xor_sync(0xffffffffu, ls0, 2);
        ls1 += __shfl_xor_sync(0xffffffffu, ls1, 1);
        ls1 += __shfl_xor_sync(0xffffffffu, ls1, 2);
        l0 = l0 * sc0 + ls0;
        l1 = l1 * sc1 + ls1;

        __syncwarp();

        // O += P V  (k over 64 keys)
        #pragma unroll
        for (int ks = 0; ks < 8; ks++) {
            int k0 = ks * 8;
            uint32_t a0 = Ps[arow0 + k0 + lc];
            uint32_t a1 = Ps[arow1 + k0 + lc];
            uint32_t a2 = Ps[arow0 + k0 + lc + 4];
            uint32_t a3 = Ps[arow1 + k0 + lc + 4];
            #pragma unroll
            for (int nt = 0; nt < 8; nt++) {
                uint32_t b0 = Vs[(k0 + lc) * DPAD + nt * 8 + lr];
                uint32_t b1 = Vs[(k0 + lc + 4) * DPAD + nt * 8 + lr];
                mma_tf32(of[nt][0], of[nt][1], of[nt][2], of[nt][3],
                         a0, a1, a2, a3, b0, b1);
            }
        }
    }

    float inv0 = 1.0f / l0, inv1 = 1.0f / l1;
    size_t r0w = ((size_t)b * SS + qb * 128 + wm + lr) * DD + h * HDIM;
    size_t r1w = r0w + (size_t)8 * DD;
    #pragma unroll
    for (int nt = 0; nt < 8; nt++) {
        float2 o0, o1;
        o0.x = of[nt][0] * inv0; o0.y = of[nt][1] * inv0;
        o1.x = of[nt][2] * inv1; o1.y = of[nt][3] * inv1;
        *(float2*)(g_ao + r0w + nt * 8 + lc * 2) = o0;
        *(float2*)(g_ao + r1w + nt * 8 + lc * 2) = o1;
    }
}

// ---------------------------------------------------------------------------
extern "C" void kernel_launch(void* const* d_in, const int* in_sizes, int n_in,
                              void* d_out, int out_size)
{
    const float* x     = (const float*)d_in[0];
    const float* amask = (const float*)d_in[1];
    const float* Wq    = (const float*)d_in[2];
    const float* bq    = (const float*)d_in[3];
    const float* Wk    = (const float*)d_in[4];
    const float* bk    = (const float*)d_in[5];
    const float* Wv    = (const float*)d_in[6];
    const float* bv    = (const float*)d_in[7];
    const float* Wo    = (const float*)d_in[8];
    const float* bo    = (const float*)d_in[9];
    const float* gam   = (const float*)d_in[10];
    const float* bet   = (const float*)d_in[11];
    float* out = (float*)d_out;

    cudaFuncSetAttribute(attn_mma,
                         cudaFuncAttributeMaxDynamicSharedMemorySize,
                         ATTN2_SMEM_BYTES);

    ln_kernel<<<MM, 256>>>(x, gam, bet);

    dim3 ggrid(DD/128, MM/128);   // (8, 64)
    gemm_mma<<<ggrid, 256>>>(Wq, bq, nullptr, nullptr, 0, 0);
    gemm_mma<<<ggrid, 256>>>(Wk, bk, nullptr, nullptr, 0, 1);
    gemm_mma<<<ggrid, 256>>>(Wv, bv, nullptr, nullptr, 0, 2);

    dim3 agrid(SS/128, BB*HH);    // (16, 64)
    attn_mma<<<agrid, 256, ATTN2_SMEM_BYTES>>>(amask);

    gemm_mma<<<ggrid, 256>>>(Wo, bo, x, out, 1, 3);
}

// round 5
// speedup vs baseline: 3.3345x; 1.1075x over previous
#include <cuda_runtime.h>
#include <cuda_bf16.h>
#include <cstdint>
#include <math.h>

// Problem constants (fixed by reference setup_inputs)
#define BB   4
#define SS   2048
#define DD   1024
#define HH   16
#define HDIM 64
#define MM   (BB*SS)          // 8192

#define NEG_BIG (-1e30f)

// Scratch (device globals: allocation-free rule)
__device__ float g_xn[MM*DD];        // tf32-rounded LN output
__device__ float g_q [MM*DD];        // [B,H,S,Hd] tf32-rounded
__device__ float g_k [MM*DD];
__device__ float g_v [MM*DD];
__device__ float g_ao[MM*DD];        // [B,S,D] tf32-rounded attn output
__device__ float g_wt[4*DD*DD];      // tf32-rounded weights (q,k,v,o)

__device__ __forceinline__ uint32_t f2tf32(float f) {
    uint32_t u;
    asm("cvt.rna.tf32.f32 %0, %1;" : "=r"(u) : "f"(f));
    return u;
}
__device__ __forceinline__ float rtf(float f) { return __uint_as_float(f2tf32(f)); }

__device__ __forceinline__ uint32_t smem_u32(const void* p) {
    uint32_t a;
    asm("{ .reg .u64 t; cvta.to.shared.u64 t, %1; cvt.u32.u64 %0, t; }" : "=r"(a) : "l"(p));
    return a;
}
#define CP_ASYNC16(dst, src) \
    asm volatile("cp.async.cg.shared.global [%0], [%1], 16;" :: "r"(dst), "l"(src))
#define CP_COMMIT() asm volatile("cp.async.commit_group;" ::: "memory")
#define CP_WAIT1()  asm volatile("cp.async.wait_group 1;" ::: "memory")
#define CP_WAIT0()  asm volatile("cp.async.wait_group 0;" ::: "memory")

__device__ __forceinline__ void mma_tf32(float& c0, float& c1, float& c2, float& c3,
                                         uint32_t a0, uint32_t a1, uint32_t a2, uint32_t a3,
                                         uint32_t b0, uint32_t b1) {
    asm volatile(
        "mma.sync.aligned.m16n8k8.row.col.f32.tf32.tf32.f32 "
        "{%0,%1,%2,%3}, {%4,%5,%6,%7}, {%8,%9}, {%0,%1,%2,%3};"
        : "+f"(c0), "+f"(c1), "+f"(c2), "+f"(c3)
        : "r"(a0), "r"(a1), "r"(a2), "r"(a3), "r"(b0), "r"(b1));
}

// ---------------------------------------------------------------------------
// Weight pre-rounding: W -> g_wt[widx] (tf32 rna)
// ---------------------------------------------------------------------------
__global__ __launch_bounds__(256) void cvtw_kernel(const float* __restrict__ w, int widx)
{
    int i = blockIdx.x * 256 + threadIdx.x;
    float4 v = ((const float4*)w)[i];
    v.x = rtf(v.x); v.y = rtf(v.y); v.z = rtf(v.z); v.w = rtf(v.w);
    ((float4*)(g_wt + (size_t)widx * DD * DD))[i] = v;
}

// ---------------------------------------------------------------------------
// LayerNorm: one block per row, 256 threads, float4. Output tf32-rounded.
// ---------------------------------------------------------------------------
__global__ __launch_bounds__(256) void ln_kernel(
    const float* __restrict__ x,
    const float* __restrict__ gamma,
    const float* __restrict__ beta)
{
    int row = blockIdx.x;
    int tid = threadIdx.x;
    const float4* xr = (const float4*)(x + (size_t)row * DD);
    float4 v = xr[tid];

    __shared__ float red[8];
    float s = v.x + v.y + v.z + v.w;
    #pragma unroll
    for (int o = 16; o > 0; o >>= 1) s += __shfl_xor_sync(0xffffffffu, s, o);
    if ((tid & 31) == 0) red[tid >> 5] = s;
    __syncthreads();
    float tot = red[0]+red[1]+red[2]+red[3]+red[4]+red[5]+red[6]+red[7];
    float mean = tot * (1.0f / DD);

    float4 d;
    d.x = v.x - mean; d.y = v.y - mean; d.z = v.z - mean; d.w = v.w - mean;
    float s2 = d.x*d.x + d.y*d.y + d.z*d.z + d.w*d.w;
    #pragma unroll
    for (int o = 16; o > 0; o >>= 1) s2 += __shfl_xor_sync(0xffffffffu, s2, o);
    __syncthreads();
    if ((tid & 31) == 0) red[tid >> 5] = s2;
    __syncthreads();
    float var = (red[0]+red[1]+red[2]+red[3]+red[4]+red[5]+red[6]+red[7]) * (1.0f / DD);
    float rstd = rsqrtf(var + 1e-5f);

    float4 g  = ((const float4*)gamma)[tid];
    float4 bb = ((const float4*)beta)[tid];
    float4 o4;
    o4.x = rtf(d.x * rstd * g.x + bb.x);
    o4.y = rtf(d.y * rstd * g.y + bb.y);
    o4.z = rtf(d.z * rstd * g.z + bb.z);
    o4.w = rtf(d.w * rstd * g.w + bb.w);
    ((float4*)(g_xn + (size_t)row * DD))[tid] = o4;
}

// ---------------------------------------------------------------------------
// Tensor-core tf32 GEMM with cp.async double-buffered smem.
// C[m,n] = sum_k A[m,k]*W[n,k] (+bias/resid). Inputs pre-rounded to tf32.
// 128x128 tile, BK=32, 256 threads (8 warps, 4m x 2n), warp tile 32x64.
// srcSel: 0 -> A = g_xn, 1 -> A = g_ao
// dstSel: 0/1/2 -> g_q/g_k/g_v [B,H,S,Hd] (tf32-rounded); 3 -> out (+resid, fp32)
// ---------------------------------------------------------------------------
#define KPAD 36
#define MWORDS (128 * KPAD)                 // words per matrix buffer
#define GEMM_SMEM_BYTES (4 * MWORDS * 4)    // A0,B0,A1,B1 = 73728

__global__ __launch_bounds__(256, 2) void gemm_mma(
    int widx,
    const float* __restrict__ bias,
    const float* __restrict__ resid,
    float* __restrict__ out,
    int srcSel, int dstSel)
{
    extern __shared__ uint32_t smem[];
    const float* A = srcSel ? g_ao : g_xn;
    const float* W = g_wt + (size_t)widx * DD * DD;

    int tid = threadIdx.x;
    int wid = tid >> 5, lane = tid & 31;
    int m0 = blockIdx.y * 128;
    int n0 = blockIdx.x * 128;

    int wm = (wid & 3) * 32;
    int wn = (wid >> 2) * 64;
    int lr = lane >> 2;
    int lc = lane & 3;

    int srow[4], sc4[4];
    uint32_t sdstA[4], sdstB[4];
    uint32_t sbase = smem_u32(smem);
    #pragma unroll
    for (int i = 0; i < 4; i++) {
        int f4 = tid + i * 256;
        srow[i] = f4 >> 3;
        sc4[i]  = f4 & 7;
        sdstA[i] = sbase + (srow[i] * KPAD + sc4[i] * 4) * 4;
        sdstB[i] = sdstA[i] + MWORDS * 4;
    }

    float acc[2][8][4];
    #pragma unroll
    for (int tm = 0; tm < 2; tm++)
        #pragma unroll
        for (int tn = 0; tn < 8; tn++)
            #pragma unroll
            for (int c = 0; c < 4; c++) acc[tm][tn][c] = 0.0f;

    // issue tile 0 into buf 0
    #pragma unroll
    for (int i = 0; i < 4; i++) {
        CP_ASYNC16(sdstA[i], A + (size_t)(m0 + srow[i]) * DD + sc4[i] * 4);
        CP_ASYNC16(sdstB[i], W + (size_t)(n0 + srow[i]) * DD + sc4[i] * 4);
    }
    CP_COMMIT();

    for (int kt = 0; kt < 32; kt++) {
        int buf = kt & 1;
        if (kt < 31) {
            int k0n = (kt + 1) * 32;
            uint32_t boff = (buf ^ 1) * 2 * MWORDS * 4;
            #pragma unroll
            for (int i = 0; i < 4; i++) {
                CP_ASYNC16(sdstA[i] + boff, A + (size_t)(m0 + srow[i]) * DD + k0n + sc4[i] * 4);
                CP_ASYNC16(sdstB[i] + boff, W + (size_t)(n0 + srow[i]) * DD + k0n + sc4[i] * 4);
            }
            CP_COMMIT();
            CP_WAIT1();
        } else {
            CP_WAIT0();
        }
        __syncthreads();

        const uint32_t* As = smem + buf * 2 * MWORDS;
        const uint32_t* Bs = As + MWORDS;

        #pragma unroll
        for (int ks = 0; ks < 4; ks++) {
            int k0 = ks * 8;
            uint32_t af[2][4];
            #pragma unroll
            for (int tm = 0; tm < 2; tm++) {
                int base = (wm + tm * 16 + lr) * KPAD + k0 + lc;
                af[tm][0] = As[base];
                af[tm][1] = As[base + 8 * KPAD];
                af[tm][2] = As[base + 4];
                af[tm][3] = As[base + 8 * KPAD + 4];
            }
            uint32_t bf[8][2];
            #pragma unroll
            for (int tn = 0; tn < 8; tn++) {
                int base = (wn + tn * 8 + lr) * KPAD + k0 + lc;
                bf[tn][0] = Bs[base];
                bf[tn][1] = Bs[base + 4];
            }
            #pragma unroll
            for (int tm = 0; tm < 2; tm++)
                #pragma unroll
                for (int tn = 0; tn < 8; tn++)
                    mma_tf32(acc[tm][tn][0], acc[tm][tn][1], acc[tm][tn][2], acc[tm][tn][3],
                             af[tm][0], af[tm][1], af[tm][2], af[tm][3],
                             bf[tn][0], bf[tn][1]);
        }
        __syncthreads();
    }

    float* hdst = (dstSel == 0) ? g_q : (dstSel == 1) ? g_k : g_v;
    #pragma unroll
    for (int tm = 0; tm < 2; tm++) {
        #pragma unroll
        for (int half = 0; half < 2; half++) {
            int m = m0 + wm + tm * 16 + lr + half * 8;
            int bI = m >> 11, sI = m & (SS - 1);
            #pragma unroll
            for (int tn = 0; tn < 8; tn++) {
                int n = n0 + wn + tn * 8 + lc * 2;
                float2 bz = *(const float2*)(bias + n);
                float2 r;
                r.x = acc[tm][tn][half*2+0] + bz.x;
                r.y = acc[tm][tn][half*2+1] + bz.y;
                if (dstSel < 3) {
                    r.x = rtf(r.x); r.y = rtf(r.y);
                    int h = n >> 6, hd = n & 63;
                    size_t idx = ((size_t)(bI * HH + h) * SS + sI) * HDIM + hd;
                    *(float2*)(hdst + idx) = r;
                } else {
                    size_t idx = (size_t)m * DD + n;
                    float2 rv = *(const float2*)(resid + idx);
                    r.x += rv.x; r.y += rv.y;
                    *(float2*)(out + idx) = r;
                }
            }
        }
    }
}

// ---------------------------------------------------------------------------
// Tensor-core causal flash attention. Inputs pre-rounded tf32.
// 128 queries x 64 keys per iteration, Hd=64, 8 warps (warp = 16 full rows).
// grid: (S/128 = 16, B*H = 64)
// ---------------------------------------------------------------------------
#define DPAD 68
#define ATTN2_SMEM_WORDS (128*DPAD + 64*DPAD + 64*DPAD + 128*DPAD + 64)
#define ATTN2_SMEM_BYTES (ATTN2_SMEM_WORDS * 4)

__global__ __launch_bounds__(256) void attn_mma(const float* __restrict__ mask)
{
    extern __shared__ uint32_t sm2[];
    uint32_t* Qs = sm2;                   // [128][DPAD]
    uint32_t* Ks = Qs + 128*DPAD;         // [64][DPAD]  K[key][d]
    uint32_t* Vs = Ks + 64*DPAD;          // [64][DPAD]  V[key][d]
    uint32_t* Ps = Vs + 64*DPAD;          // [128][DPAD]
    float*    mv = (float*)(Ps + 128*DPAD);

    int qb = (int)gridDim.x - 1 - (int)blockIdx.x;   // heavy blocks first
    int bh = blockIdx.y;
    int b = bh >> 4, h = bh & 15;

    const float* Qg = g_q + ((size_t)bh * SS + qb * 128) * HDIM;
    const float* Kg = g_k + (size_t)bh * SS * HDIM;
    const float* Vg = g_v + (size_t)bh * SS * HDIM;

    int tid = threadIdx.x;
    int wid = tid >> 5, lane = tid & 31;
    int lr = lane >> 2, lc = lane & 3;
    int wm = wid * 16;

    // stage Q (already tf32 bits)
    #pragma unroll
    for (int i = 0; i < 8; i++) {
        int f4 = tid + i * 256;
        int row = f4 >> 4, c4 = f4 & 15;
        uint4 t = *(const uint4*)(Qg + row * HDIM + c4 * 4);
        *(uint4*)(Qs + row * DPAD + c4 * 4) = t;
    }

    float of[8][4];
    #pragma unroll
    for (int nt = 0; nt < 8; nt++)
        #pragma unroll
        for (int c = 0; c < 4; c++) of[nt][c] = 0.0f;
    float m0 = NEG_BIG, m1 = NEG_BIG, l0 = 0.0f, l1 = 0.0f;

    int row_g0 = qb * 128 + wm + lr;
    int row_g1 = row_g0 + 8;
    int arow0 = (wm + lr) * DPAD;
    int arow1 = (wm + lr + 8) * DPAD;

    int jbmax = 2 * qb + 1;
    for (int jb = 0; jb <= jbmax; jb++) {
        __syncthreads();
        #pragma unroll
        for (int i = 0; i < 4; i++) {
            int f4 = tid + i * 256;
            int row = f4 >> 4, c4 = f4 & 15;
            uint4 kt4 = *(const uint4*)(Kg + (size_t)(jb * 64 + row) * HDIM + c4 * 4);
            uint4 vt4 = *(const uint4*)(Vg + (size_t)(jb * 64 + row) * HDIM + c4 * 4);
            *(uint4*)(Ks + row * DPAD + c4 * 4) = kt4;
            *(uint4*)(Vs + row * DPAD + c4 * 4) = vt4;
        }
        if (tid < 64) mv[tid] = mask[b * SS + jb * 64 + tid];
        __syncthreads();

        float sf[8][4];
        #pragma unroll
        for (int nt = 0; nt < 8; nt++)
            #pragma unroll
            for (int c = 0; c < 4; c++) sf[nt][c] = 0.0f;

        #pragma unroll
        for (int ks = 0; ks < 8; ks++) {
            int k0 = ks * 8;
            uint32_t a0 = Qs[arow0 + k0 + lc];
            uint32_t a1 = Qs[arow1 + k0 + lc];
            uint32_t a2 = Qs[arow0 + k0 + lc + 4];
            uint32_t a3 = Qs[arow1 + k0 + lc + 4];
            #pragma unroll
            for (int nt = 0; nt < 8; nt++) {
                uint32_t b0 = Ks[(nt * 8 + lr) * DPAD + k0 + lc];
                uint32_t b1 = Ks[(nt * 8 + lr) * DPAD + k0 + lc + 4];
                mma_tf32(sf[nt][0], sf[nt][1], sf[nt][2], sf[nt][3],
                         a0, a1, a2, a3, b0, b1);
            }
        }

        float rmax0 = NEG_BIG, rmax1 = NEG_BIG;
        #pragma unroll
        for (int nt = 0; nt < 8; nt++) {
            int cg = jb * 64 + nt * 8 + lc * 2;
            float pma = -10000.0f * (1.0f - mv[nt * 8 + lc * 2]);
            float pmb = -10000.0f * (1.0f - mv[nt * 8 + lc * 2 + 1]);
            float v0 = sf[nt][0] * 0.125f + pma; if (cg     > row_g0) v0 = NEG_BIG;
            float v1 = sf[nt][1] * 0.125f + pmb; if (cg + 1 > row_g0) v1 = NEG_BIG;
            float v2 = sf[nt][2] * 0.125f + pma; if (cg     > row_g1) v2 = NEG_BIG;
            float v3 = sf[nt][3] * 0.125f + pmb; if (cg + 1 > row_g1) v3 = NEG_BIG;
            sf[nt][0] = v0; sf[nt][1] = v1; sf[nt][2] = v2; sf[nt][3] = v3;
            rmax0 = fmaxf(rmax0, fmaxf(v0, v1));
            rmax1 = fmaxf(rmax1, fmaxf(v2, v3));
        }
        rmax0 = fmaxf(rmax0, __shfl_xor_sync(0xffffffffu, rmax0, 1));
        rmax0 = fmaxf(rmax0, __shfl_xor_sync(0xffffffffu, rmax0, 2));
        rmax1 = fmaxf(rmax1, __shfl_xor_sync(0xffffffffu, rmax1, 1));
        rmax1 = fmaxf(rmax1, __shfl_xor_sync(0xffffffffu, rmax1, 2));

        float mn0 = fmaxf(m0, rmax0), mn1 = fmaxf(m1, rmax1);
        float sc0 = __expf(m0 - mn0), sc1 = __expf(m1 - mn1);
        m0 = mn0; m1 = mn1;

        float ls0 = 0.0f, ls1 = 0.0f;
        #pragma unroll
        for (int nt = 0; nt < 8; nt++) {
            float p0 = __expf(sf[nt][0] - mn0);
            float p1 = __expf(sf[nt][1] - mn0);
            float p2 = __expf(sf[nt][2] - mn1);
            float p3 = __expf(sf[nt][3] - mn1);
            ls0 += p0 + p1; ls1 += p2 + p3;
            uint2 w0; w0.x = f2tf32(p0); w0.y = f2tf32(p1);
            uint2 w1; w1.x = f2tf32(p2); w1.y = f2tf32(p3);
            *(uint2*)(Ps + arow0 + nt * 8 + lc * 2) = w0;
            *(uint2*)(Ps + arow1 + nt * 8 + lc * 2) = w1;
            of[nt][0] *= sc0; of[nt][1] *= sc0;
            of[nt][2] *= sc1; of[nt][3] *= sc1;
        }
        ls0 += __shfl_xor_sync(0xffffffffu, ls0, 1);
        ls0 += __shfl_xor_sync(0xffffffffu, ls0, 2);
        ls1 += __shfl_xor_sync(0xffffffffu, ls1, 1);
        ls1 += __shfl_xor_sync(0xffffffffu, ls1, 2);
        l0 = l0 * sc0 + ls0;
        l1 = l1 * sc1 + ls1;

        __syncwarp();

        #pragma unroll
        for (int ks = 0; ks < 8; ks++) {
            int k0 = ks * 8;
            uint32_t a0 = Ps[arow0 + k0 + lc];
            uint32_t a1 = Ps[arow1 + k0 + lc];
            uint32_t a2 = Ps[arow0 + k0 + lc + 4];
            uint32_t a3 = Ps[arow1 + k0 + lc + 4];
            #pragma unroll
            for (int nt = 0; nt < 8; nt++) {
                uint32_t b0 = Vs[(k0 + lc) * DPAD + nt * 8 + lr];
                uint32_t b1 = Vs[(k0 + lc + 4) * DPAD + nt * 8 + lr];
                mma_tf32(of[nt][0], of[nt][1], of[nt][2], of[nt][3],
                         a0, a1, a2, a3, b0, b1);
            }
        }
    }

    float inv0 = 1.0f / l0, inv1 = 1.0f / l1;
    size_t r0w = ((size_t)b * SS + qb * 128 + wm + lr) * DD + h * HDIM;
    size_t r1w = r0w + (size_t)8 * DD;
    #pragma unroll
    for (int nt = 0; nt < 8; nt++) {
        float2 o0, o1;
        o0.x = rtf(of[nt][0] * inv0); o0.y = rtf(of[nt][1] * inv0);
        o1.x = rtf(of[nt][2] * inv1); o1.y = rtf(of[nt][3] * inv1);
        *(float2*)(g_ao + r0w + nt * 8 + lc * 2) = o0;
        *(float2*)(g_ao + r1w + nt * 8 + lc * 2) = o1;
    }
}

// ---------------------------------------------------------------------------
extern "C" void kernel_launch(void* const* d_in, const int* in_sizes, int n_in,
                              void* d_out, int out_size)
{
    const float* x     = (const float*)d_in[0];
    const float* amask = (const float*)d_in[1];
    const float* Wq    = (const float*)d_in[2];
    const float* bq    = (const float*)d_in[3];
    const float* Wk    = (const float*)d_in[4];
    const float* bk    = (const float*)d_in[5];
    const float* Wv    = (const float*)d_in[6];
    const float* bv    = (const float*)d_in[7];
    const float* Wo    = (const float*)d_in[8];
    const float* bo    = (const float*)d_in[9];
    const float* gam   = (const float*)d_in[10];
    const float* bet   = (const float*)d_in[11];
    float* out = (float*)d_out;

    cudaFuncSetAttribute(attn_mma,
                         cudaFuncAttributeMaxDynamicSharedMemorySize,
                         ATTN2_SMEM_BYTES);
    cudaFuncSetAttribute(gemm_mma,
                         cudaFuncAttributeMaxDynamicSharedMemorySize,
                         GEMM_SMEM_BYTES);

    int cvtg = DD * DD / 4 / 256;   // 1024
    cvtw_kernel<<<cvtg, 256>>>(Wq, 0);
    cvtw_kernel<<<cvtg, 256>>>(Wk, 1);
    cvtw_kernel<<<cvtg, 256>>>(Wv, 2);
    cvtw_kernel<<<cvtg, 256>>>(Wo, 3);

    ln_kernel<<<MM, 256>>>(x, gam, bet);

    dim3 ggrid(DD/128, MM/128);   // (8, 64)
    gemm_mma<<<ggrid, 256, GEMM_SMEM_BYTES>>>(0, bq, nullptr, nullptr, 0, 0);
    gemm_mma<<<ggrid, 256, GEMM_SMEM_BYTES>>>(1, bk, nullptr, nullptr, 0, 1);
    gemm_mma<<<ggrid, 256, GEMM_SMEM_BYTES>>>(2, bv, nullptr, nullptr, 0, 2);

    dim3 agrid(SS/128, BB*HH);    // (16, 64)
    attn_mma<<<agrid, 256, ATTN2_SMEM_BYTES>>>(amask);

    gemm_mma<<<ggrid, 256, GEMM_SMEM_BYTES>>>(3, bo, x, out, 1, 3);
}

// round 6
// speedup vs baseline: 6.0675x; 1.8196x over previous
#include <cuda_runtime.h>
#include <cuda_fp16.h>
#include <cstdint>
#include <math.h>

#define BB   4
#define SS   2048
#define DD   1024
#define HH   16
#define HDIM 64
#define MM   (BB*SS)          // 8192

#define NEG_BIG (-1e30f)

// Scratch (device globals)
__device__ __half g_xn[MM*DD];        // LN output, fp16
__device__ __half g_q [MM*DD];        // [B,H,S,Hd]
__device__ __half g_k [MM*DD];        // [B,H,S,Hd]
__device__ __half g_v [MM*DD];        // [B,H,Hd,S]  (head-transposed!)
__device__ __half g_ao[MM*DD];        // [B,S,D]
__device__ __half g_wt[4*DD*DD];      // fp16 weights (q,k,v,o contiguous)
__device__ float  g_bias[3*DD];       // combined qkv bias

__device__ __forceinline__ uint32_t smem_u32(const void* p) {
    uint32_t a;
    asm("{ .reg .u64 t; cvta.to.shared.u64 t, %1; cvt.u32.u64 %0, t; }" : "=r"(a) : "l"(p));
    return a;
}
#define CP_ASYNC16(dst, src) \
    asm volatile("cp.async.cg.shared.global [%0], [%1], 16;" :: "r"(dst), "l"(src))
#define CP_COMMIT() asm volatile("cp.async.commit_group;" ::: "memory")
#define CP_WAIT1()  asm volatile("cp.async.wait_group 1;" ::: "memory")
#define CP_WAIT0()  asm volatile("cp.async.wait_group 0;" ::: "memory")

__device__ __forceinline__ void mma_f16(float& c0, float& c1, float& c2, float& c3,
                                        uint32_t a0, uint32_t a1, uint32_t a2, uint32_t a3,
                                        uint32_t b0, uint32_t b1) {
    asm volatile(
        "mma.sync.aligned.m16n8k16.row.col.f32.f16.f16.f32 "
        "{%0,%1,%2,%3}, {%4,%5,%6,%7}, {%8,%9}, {%0,%1,%2,%3};"
        : "+f"(c0), "+f"(c1), "+f"(c2), "+f"(c3)
        : "r"(a0), "r"(a1), "r"(a2), "r"(a3), "r"(b0), "r"(b1));
}

// ---------------------------------------------------------------------------
// Prep: weights fp32 -> fp16
// ---------------------------------------------------------------------------
__global__ __launch_bounds__(256) void cvtw_kernel(const float* __restrict__ w, int widx)
{
    int i = blockIdx.x * 256 + threadIdx.x;
    float4 v = ((const float4*)w)[i];
    __half2 h01 = __floats2half2_rn(v.x, v.y);
    __half2 h23 = __floats2half2_rn(v.z, v.w);
    uint2 u; u.x = *(uint32_t*)&h01; u.y = *(uint32_t*)&h23;
    ((uint2*)(g_wt + (size_t)widx * DD * DD))[i] = u;
}

__global__ __launch_bounds__(256) void bias_kernel(
    const float* __restrict__ bq, const float* __restrict__ bk, const float* __restrict__ bv)
{
    int i = blockIdx.x * 256 + threadIdx.x;   // 0..3071
    const float* src = (i < DD) ? bq : (i < 2*DD) ? bk : bv;
    g_bias[i] = src[i & (DD-1)];
}

// ---------------------------------------------------------------------------
// LayerNorm: one block per row, 256 threads. Output fp16.
// ---------------------------------------------------------------------------
__global__ __launch_bounds__(256) void ln_kernel(
    const float* __restrict__ x,
    const float* __restrict__ gamma,
    const float* __restrict__ beta)
{
    int row = blockIdx.x;
    int tid = threadIdx.x;
    const float4* xr = (const float4*)(x + (size_t)row * DD);
    float4 v = xr[tid];

    __shared__ float red[8];
    float s = v.x + v.y + v.z + v.w;
    #pragma unroll
    for (int o = 16; o > 0; o >>= 1) s += __shfl_xor_sync(0xffffffffu, s, o);
    if ((tid & 31) == 0) red[tid >> 5] = s;
    __syncthreads();
    float tot = red[0]+red[1]+red[2]+red[3]+red[4]+red[5]+red[6]+red[7];
    float mean = tot * (1.0f / DD);

    float4 d;
    d.x = v.x - mean; d.y = v.y - mean; d.z = v.z - mean; d.w = v.w - mean;
    float s2 = d.x*d.x + d.y*d.y + d.z*d.z + d.w*d.w;
    #pragma unroll
    for (int o = 16; o > 0; o >>= 1) s2 += __shfl_xor_sync(0xffffffffu, s2, o);
    __syncthreads();
    if ((tid & 31) == 0) red[tid >> 5] = s2;
    __syncthreads();
    float var = (red[0]+red[1]+red[2]+red[3]+red[4]+red[5]+red[6]+red[7]) * (1.0f / DD);
    float rstd = rsqrtf(var + 1e-5f);

    float4 g  = ((const float4*)gamma)[tid];
    float4 bb = ((const float4*)beta)[tid];
    __half2 h01 = __floats2half2_rn(d.x * rstd * g.x + bb.x, d.y * rstd * g.y + bb.y);
    __half2 h23 = __floats2half2_rn(d.z * rstd * g.z + bb.z, d.w * rstd * g.w + bb.w);
    uint2 u; u.x = *(uint32_t*)&h01; u.y = *(uint32_t*)&h23;
    ((uint2*)(g_xn + (size_t)row * DD))[tid] = u;
}

// ---------------------------------------------------------------------------
// fp16 tensor GEMM, cp.async double buffered.
// C[m,n] = sum_k A[m,k]*W[n,k]. 128x128 tile, BK=32 halfs, 8 warps (4m x 2n).
// mode 0: fused QKV (W = g_wt, bias = g_bias, n in [0,3072), scatter q/k/v)
// mode 1: output GEMM (W = g_wt+3*DD*DD, bias=bo, resid add, fp32 out)
// ---------------------------------------------------------------------------
#define KP2 20
#define MW2 (128 * KP2)                   // words per matrix buffer
#define GEMM_SMEM_BYTES (4 * MW2 * 4)     // 40960

__global__ __launch_bounds__(256, 2) void gemm_h(
    int mode,
    const float* __restrict__ bias_o,
    const float* __restrict__ resid,
    float* __restrict__ out)
{
    extern __shared__ uint32_t smem[];
    const __half* A = mode ? g_ao : g_xn;
    const __half* W = mode ? (g_wt + (size_t)3 * DD * DD) : g_wt;

    int tid = threadIdx.x;
    int wid = tid >> 5, lane = tid & 31;
    int m0 = blockIdx.y * 128;
    int n0 = blockIdx.x * 128;

    int wm = (wid & 3) * 32;
    int wn = (wid >> 2) * 64;
    int lr = lane >> 2;
    int lc = lane & 3;

    int srow[2], sc4[2];
    uint32_t sdstA[2], sdstB[2];
    uint32_t sbase = smem_u32(smem);
    #pragma unroll
    for (int i = 0; i < 2; i++) {
        int f = tid + i * 256;         // 0..511
        srow[i] = f >> 2;              // 0..127
        sc4[i]  = f & 3;               // 16B chunk within 64B row
        sdstA[i] = sbase + (srow[i] * KP2 + sc4[i] * 4) * 4;
        sdstB[i] = sdstA[i] + MW2 * 4;
    }

    float acc[2][8][4];
    #pragma unroll
    for (int tm = 0; tm < 2; tm++)
        #pragma unroll
        for (int tn = 0; tn < 8; tn++)
            #pragma unroll
            for (int c = 0; c < 4; c++) acc[tm][tn][c] = 0.0f;

    #pragma unroll
    for (int i = 0; i < 2; i++) {
        CP_ASYNC16(sdstA[i], A + (size_t)(m0 + srow[i]) * DD + sc4[i] * 8);
        CP_ASYNC16(sdstB[i], W + (size_t)(n0 + srow[i]) * DD + sc4[i] * 8);
    }
    CP_COMMIT();

    for (int kt = 0; kt < 32; kt++) {
        int buf = kt & 1;
        if (kt < 31) {
            int k0n = (kt + 1) * 32;
            uint32_t boff = (buf ^ 1) * 2 * MW2 * 4;
            #pragma unroll
            for (int i = 0; i < 2; i++) {
                CP_ASYNC16(sdstA[i] + boff, A + (size_t)(m0 + srow[i]) * DD + k0n + sc4[i] * 8);
                CP_ASYNC16(sdstB[i] + boff, W + (size_t)(n0 + srow[i]) * DD + k0n + sc4[i] * 8);
            }
            CP_COMMIT();
            CP_WAIT1();
        } else {
            CP_WAIT0();
        }
        __syncthreads();

        const uint32_t* As = smem + buf * 2 * MW2;
        const uint32_t* Bs = As + MW2;

        #pragma unroll
        for (int ks = 0; ks < 2; ks++) {
            int k0 = ks * 8;
            uint32_t af[2][4];
            #pragma unroll
            for (int tm = 0; tm < 2; tm++) {
                int base = (wm + tm * 16 + lr) * KP2 + k0 + lc;
                af[tm][0] = As[base];
                af[tm][1] = As[base + 8 * KP2];
                af[tm][2] = As[base + 4];
                af[tm][3] = As[base + 8 * KP2 + 4];
            }
            uint32_t bf[8][2];
            #pragma unroll
            for (int tn = 0; tn < 8; tn++) {
                int base = (wn + tn * 8 + lr) * KP2 + k0 + lc;
                bf[tn][0] = Bs[base];
                bf[tn][1] = Bs[base + 4];
            }
            #pragma unroll
            for (int tm = 0; tm < 2; tm++)
                #pragma unroll
                for (int tn = 0; tn < 8; tn++)
                    mma_f16(acc[tm][tn][0], acc[tm][tn][1], acc[tm][tn][2], acc[tm][tn][3],
                            af[tm][0], af[tm][1], af[tm][2], af[tm][3],
                            bf[tn][0], bf[tn][1]);
        }
        __syncthreads();
    }

    #pragma unroll
    for (int tm = 0; tm < 2; tm++) {
        #pragma unroll
        for (int half = 0; half < 2; half++) {
            int m = m0 + wm + tm * 16 + lr + half * 8;
            int bI = m >> 11, sI = m & (SS - 1);
            #pragma unroll
            for (int tn = 0; tn < 8; tn++) {
                int n = n0 + wn + tn * 8 + lc * 2;
                float r0 = acc[tm][tn][half*2+0];
                float r1 = acc[tm][tn][half*2+1];
                if (mode == 0) {
                    r0 += g_bias[n]; r1 += g_bias[n+1];
                    int sel = n >> 10;            // 0=q,1=k,2=v
                    int nn = n & (DD - 1);
                    int h = nn >> 6, hd = nn & 63;
                    if (sel < 2) {
                        __half2 hv = __floats2half2_rn(r0, r1);
                        __half* dst = (sel == 0) ? g_q : g_k;
                        size_t idx = ((size_t)(bI * HH + h) * SS + sI) * HDIM + hd;
                        *(__half2*)(dst + idx) = hv;
                    } else {
                        // V transposed: [B,H,Hd,S]
                        size_t base = ((size_t)(bI * HH + h) * HDIM + hd) * SS + sI;
                        g_v[base]      = __float2half_rn(r0);
                        g_v[base + SS] = __float2half_rn(r1);
                    }
                } else {
                    float2 bz = *(const float2*)(bias_o + n);
                    size_t idx = (size_t)m * DD + n;
                    float2 rv = *(const float2*)(resid + idx);
                    float2 r;
                    r.x = r0 + bz.x + rv.x;
                    r.y = r1 + bz.y + rv.y;
                    *(float2*)(out + idx) = r;
                }
            }
        }
    }
}

// ---------------------------------------------------------------------------
// fp16 tensor-core causal flash attention.
// 128 queries x 64 keys per iter, Hd=64, 8 warps (warp = 16 rows).
// grid: (S/128 = 16, B*H = 64)
// ---------------------------------------------------------------------------
#define KQ 36
#define ATTN_WORDS (128*KQ + 64*KQ + 64*KQ + 128*KQ + 64)
#define ATTN_SMEM_BYTES (ATTN_WORDS * 4)

__global__ __launch_bounds__(256) void attn_h(const float* __restrict__ mask)
{
    extern __shared__ uint32_t sm2[];
    uint32_t* Qs = sm2;                   // [128][KQ] half2 words, k packed
    uint32_t* Ks = Qs + 128*KQ;           // [64][KQ]  K[key][d]
    uint32_t* Vt = Ks + 64*KQ;            // [64][KQ]  V[d][key] (key pairs packed)
    uint32_t* Ps = Vt + 64*KQ;            // [128][KQ]
    float*    mv = (float*)(Ps + 128*KQ);

    int qb = (int)gridDim.x - 1 - (int)blockIdx.x;   // heavy blocks first
    int bh = blockIdx.y;
    int b = bh >> 4, h = bh & 15;

    const __half* Qg = g_q + ((size_t)bh * SS + qb * 128) * HDIM;
    const __half* Kg = g_k + (size_t)bh * SS * HDIM;
    const __half* Vg = g_v + (size_t)bh * HDIM * SS;   // [d][s]

    int tid = threadIdx.x;
    int wid = tid >> 5, lane = tid & 31;
    int lr = lane >> 2, lc = lane & 3;
    int wm = wid * 16;

    // stage Q: 128 rows x 32 words (uint4 = 4 words)
    #pragma unroll
    for (int i = 0; i < 4; i++) {
        int c = tid + i * 256;           // 0..1023
        int row = c >> 3, w4 = c & 7;
        uint4 t = *(const uint4*)(Qg + row * HDIM + w4 * 8);
        *(uint4*)(Qs + row * KQ + w4 * 4) = t;
    }

    float of[8][4];
    #pragma unroll
    for (int nt = 0; nt < 8; nt++)
        #pragma unroll
        for (int c = 0; c < 4; c++) of[nt][c] = 0.0f;
    float m0 = NEG_BIG, m1 = NEG_BIG, l0 = 0.0f, l1 = 0.0f;

    int row_g0 = qb * 128 + wm + lr;
    int row_g1 = row_g0 + 8;
    int arow0 = (wm + lr) * KQ;
    int arow1 = (wm + lr + 8) * KQ;

    int jbmax = 2 * qb + 1;
    for (int jb = 0; jb <= jbmax; jb++) {
        __syncthreads();
        // K rows: 64 x 8 uint4 = 512 chunks; Vt rows (d): 64 x 8 uint4
        #pragma unroll
        for (int i = 0; i < 2; i++) {
            int c = tid + i * 256;       // 0..511
            int row = c >> 3, w4 = c & 7;
            uint4 kt4 = *(const uint4*)(Kg + (size_t)(jb * 64 + row) * HDIM + w4 * 8);
            *(uint4*)(Ks + row * KQ + w4 * 4) = kt4;
            uint4 vt4 = *(const uint4*)(Vg + (size_t)row * SS + jb * 64 + w4 * 8);
            *(uint4*)(Vt + row * KQ + w4 * 4) = vt4;
        }
        if (tid < 64) mv[tid] = mask[b * SS + jb * 64 + tid];
        __syncthreads();

        // S = Q K^T
        float sf[8][4];
        #pragma unroll
        for (int nt = 0; nt < 8; nt++)
            #pragma unroll
            for (int c = 0; c < 4; c++) sf[nt][c] = 0.0f;

        #pragma unroll
        for (int ks = 0; ks < 4; ks++) {
            int k0 = ks * 8;
            uint32_t a0 = Qs[arow0 + k0 + lc];
            uint32_t a1 = Qs[arow1 + k0 + lc];
            uint32_t a2 = Qs[arow0 + k0 + lc + 4];
            uint32_t a3 = Qs[arow1 + k0 + lc + 4];
            #pragma unroll
            for (int nt = 0; nt < 8; nt++) {
                uint32_t b0 = Ks[(nt * 8 + lr) * KQ + k0 + lc];
                uint32_t b1 = Ks[(nt * 8 + lr) * KQ + k0 + lc + 4];
                mma_f16(sf[nt][0], sf[nt][1], sf[nt][2], sf[nt][3],
                        a0, a1, a2, a3, b0, b1);
            }
        }

        float rmax0 = NEG_BIG, rmax1 = NEG_BIG;
        #pragma unroll
        for (int nt = 0; nt < 8; nt++) {
            int cg = jb * 64 + nt * 8 + lc * 2;
            float pma = -10000.0f * (1.0f - mv[nt * 8 + lc * 2]);
            float pmb = -10000.0f * (1.0f - mv[nt * 8 + lc * 2 + 1]);
            float v0 = sf[nt][0] * 0.125f + pma; if (cg     > row_g0) v0 = NEG_BIG;
            float v1 = sf[nt][1] * 0.125f + pmb; if (cg + 1 > row_g0) v1 = NEG_BIG;
            float v2 = sf[nt][2] * 0.125f + pma; if (cg     > row_g1) v2 = NEG_BIG;
            float v3 = sf[nt][3] * 0.125f + pmb; if (cg + 1 > row_g1) v3 = NEG_BIG;
            sf[nt][0] = v0; sf[nt][1] = v1; sf[nt][2] = v2; sf[nt][3] = v3;
            rmax0 = fmaxf(rmax0, fmaxf(v0, v1));
            rmax1 = fmaxf(rmax1, fmaxf(v2, v3));
        }
        rmax0 = fmaxf(rmax0, __shfl_xor_sync(0xffffffffu, rmax0, 1));
        rmax0 = fmaxf(rmax0, __shfl_xor_sync(0xffffffffu, rmax0, 2));
        rmax1 = fmaxf(rmax1, __shfl_xor_sync(0xffffffffu, rmax1, 1));
        rmax1 = fmaxf(rmax1, __shfl_xor_sync(0xffffffffu, rmax1, 2));

        float mn0 = fmaxf(m0, rmax0), mn1 = fmaxf(m1, rmax1);
        float sc0 = __expf(m0 - mn0), sc1 = __expf(m1 - mn1);
        m0 = mn0; m1 = mn1;

        float ls0 = 0.0f, ls1 = 0.0f;
        #pragma unroll
        for (int nt = 0; nt < 8; nt++) {
            float p0 = __expf(sf[nt][0] - mn0);
            float p1 = __expf(sf[nt][1] - mn0);
            float p2 = __expf(sf[nt][2] - mn1);
            float p3 = __expf(sf[nt][3] - mn1);
            ls0 += p0 + p1; ls1 += p2 + p3;
            __half2 w0 = __floats2half2_rn(p0, p1);
            __half2 w1 = __floats2half2_rn(p2, p3);
            Ps[arow0 + nt * 4 + lc] = *(uint32_t*)&w0;
            Ps[arow1 + nt * 4 + lc] = *(uint32_t*)&w1;
            of[nt][0] *= sc0; of[nt][1] *= sc0;
            of[nt][2] *= sc1; of[nt][3] *= sc1;
        }
        ls0 += __shfl_xor_sync(0xffffffffu, ls0, 1);
        ls0 += __shfl_xor_sync(0xffffffffu, ls0, 2);
        ls1 += __shfl_xor_sync(0xffffffffu, ls1, 1);
        ls1 += __shfl_xor_sync(0xffffffffu, ls1, 2);
        l0 = l0 * sc0 + ls0;
        l1 = l1 * sc1 + ls1;

        __syncwarp();

        // O += P V   (A = P [q][key], B = Vt [d][key] col-major over key)
        #pragma unroll
        for (int ks = 0; ks < 4; ks++) {
            int k0 = ks * 8;
            uint32_t a0 = Ps[arow0 + k0 + lc];
            uint32_t a1 = Ps[arow1 + k0 + lc];
            uint32_t a2 = Ps[arow0 + k0 + lc + 4];
            uint32_t a3 = Ps[arow1 + k0 + lc + 4];
            #pragma unroll
            for (int nt = 0; nt < 8; nt++) {
                uint32_t b0 = Vt[(nt * 8 + lr) * KQ + k0 + lc];
                uint32_t b1 = Vt[(nt * 8 + lr) * KQ + k0 + lc + 4];
                mma_f16(of[nt][0], of[nt][1], of[nt][2], of[nt][3],
                        a0, a1, a2, a3, b0, b1);
            }
        }
    }

    float inv0 = 1.0f / l0, inv1 = 1.0f / l1;
    size_t r0w = ((size_t)b * SS + qb * 128 + wm + lr) * DD + h * HDIM;
    size_t r1w = r0w + (size_t)8 * DD;
    #pragma unroll
    for (int nt = 0; nt < 8; nt++) {
        __half2 o0 = __floats2half2_rn(of[nt][0] * inv0, of[nt][1] * inv0);
        __half2 o1 = __floats2half2_rn(of[nt][2] * inv1, of[nt][3] * inv1);
        *(__half2*)(g_ao + r0w + nt * 8 + lc * 2) = o0;
        *(__half2*)(g_ao + r1w + nt * 8 + lc * 2) = o1;
    }
}

// ---------------------------------------------------------------------------
extern "C" void kernel_launch(void* const* d_in, const int* in_sizes, int n_in,
                              void* d_out, int out_size)
{
    const float* x     = (const float*)d_in[0];
    const float* amask = (const float*)d_in[1];
    const float* Wq    = (const float*)d_in[2];
    const float* bq    = (const float*)d_in[3];
    const float* Wk    = (const float*)d_in[4];
    const float* bk    = (const float*)d_in[5];
    const float* Wv    = (const float*)d_in[6];
    const float* bv    = (const float*)d_in[7];
    const float* Wo    = (const float*)d_in[8];
    const float* bo    = (const float*)d_in[9];
    const float* gam   = (const float*)d_in[10];
    const float* bet   = (const float*)d_in[11];
    float* out = (float*)d_out;

    cudaFuncSetAttribute(attn_h,
                         cudaFuncAttributeMaxDynamicSharedMemorySize,
                         ATTN_SMEM_BYTES);
    cudaFuncSetAttribute(gemm_h,
                         cudaFuncAttributeMaxDynamicSharedMemorySize,
                         GEMM_SMEM_BYTES);

    int cvtg = DD * DD / 4 / 256;   // 1024
    cvtw_kernel<<<cvtg, 256>>>(Wq, 0);
    cvtw_kernel<<<cvtg, 256>>>(Wk, 1);
    cvtw_kernel<<<cvtg, 256>>>(Wv, 2);
    cvtw_kernel<<<cvtg, 256>>>(Wo, 3);
    bias_kernel<<<12, 256>>>(bq, bk, bv);

    ln_kernel<<<MM, 256>>>(x, gam, bet);

    dim3 qkvgrid(3*DD/128, MM/128);   // (24, 64)
    gemm_h<<<qkvgrid, 256, GEMM_SMEM_BYTES>>>(0, nullptr, nullptr, nullptr);

    dim3 agrid(SS/128, BB*HH);        // (16, 64)
    attn_h<<<agrid, 256, ATTN_SMEM_BYTES>>>(amask);

    dim3 ogrid(DD/128, MM/128);       // (8, 64)
    gemm_h<<<ogrid, 256, GEMM_SMEM_BYTES>>>(1, bo, x, out);
}

// round 7
// speedup vs baseline: 6.0740x; 1.0011x over previous
#include <cuda_runtime.h>
#include <cuda_fp16.h>
#include <cstdint>
#include <math.h>

#define BB   4
#define SS   2048
#define DD   1024
#define HH   16
#define HDIM 64
#define MM   (BB*SS)          // 8192

#define NEG_BIG (-1e30f)

// Scratch (device globals)
__device__ __half g_xn[MM*DD];        // LN output, fp16
__device__ __half g_q [MM*DD];        // [B,H,S,Hd]
__device__ __half g_k [MM*DD];        // [B,H,S,Hd]
__device__ __half g_v [MM*DD];        // [B,H,Hd,S]  (head-transposed!)
__device__ __half g_ao[MM*DD];        // [B,S,D]
__device__ __half g_wt[4*DD*DD];      // fp16 weights (q,k,v,o contiguous)
__device__ float  g_bias[3*DD];       // combined qkv bias

__device__ __forceinline__ uint32_t smem_u32(const void* p) {
    uint32_t a;
    asm("{ .reg .u64 t; cvta.to.shared.u64 t, %1; cvt.u32.u64 %0, t; }" : "=r"(a) : "l"(p));
    return a;
}
#define CP_ASYNC16(dst, src) \
    asm volatile("cp.async.cg.shared.global [%0], [%1], 16;" :: "r"(dst), "l"(src))
#define CP_COMMIT() asm volatile("cp.async.commit_group;" ::: "memory")
#define CP_WAIT1()  asm volatile("cp.async.wait_group 1;" ::: "memory")
#define CP_WAIT0()  asm volatile("cp.async.wait_group 0;" ::: "memory")

__device__ __forceinline__ void mma_f16(float& c0, float& c1, float& c2, float& c3,
                                        uint32_t a0, uint32_t a1, uint32_t a2, uint32_t a3,
                                        uint32_t b0, uint32_t b1) {
    asm volatile(
        "mma.sync.aligned.m16n8k16.row.col.f32.f16.f16.f32 "
        "{%0,%1,%2,%3}, {%4,%5,%6,%7}, {%8,%9}, {%0,%1,%2,%3};"
        : "+f"(c0), "+f"(c1), "+f"(c2), "+f"(c3)
        : "r"(a0), "r"(a1), "r"(a2), "r"(a3), "r"(b0), "r"(b1));
}

// ---------------------------------------------------------------------------
// Prep: weights fp32 -> fp16
// ---------------------------------------------------------------------------
__global__ __launch_bounds__(256) void cvtw_kernel(const float* __restrict__ w, int widx)
{
    int i = blockIdx.x * 256 + threadIdx.x;
    float4 v = ((const float4*)w)[i];
    __half2 h01 = __floats2half2_rn(v.x, v.y);
    __half2 h23 = __floats2half2_rn(v.z, v.w);
    uint2 u; u.x = *(uint32_t*)&h01; u.y = *(uint32_t*)&h23;
    ((uint2*)(g_wt + (size_t)widx * DD * DD))[i] = u;
}

__global__ __launch_bounds__(256) void bias_kernel(
    const float* __restrict__ bq, const float* __restrict__ bk, const float* __restrict__ bv)
{
    int i = blockIdx.x * 256 + threadIdx.x;   // 0..3071
    const float* src = (i < DD) ? bq : (i < 2*DD) ? bk : bv;
    g_bias[i] = src[i & (DD-1)];
}

// ---------------------------------------------------------------------------
// LayerNorm: one block per row, 256 threads. Output fp16.
// ---------------------------------------------------------------------------
__global__ __launch_bounds__(256) void ln_kernel(
    const float* __restrict__ x,
    const float* __restrict__ gamma,
    const float* __restrict__ beta)
{
    int row = blockIdx.x;
    int tid = threadIdx.x;
    const float4* xr = (const float4*)(x + (size_t)row * DD);
    float4 v = xr[tid];

    __shared__ float red[8];
    float s = v.x + v.y + v.z + v.w;
    #pragma unroll
    for (int o = 16; o > 0; o >>= 1) s += __shfl_xor_sync(0xffffffffu, s, o);
    if ((tid & 31) == 0) red[tid >> 5] = s;
    __syncthreads();
    float tot = red[0]+red[1]+red[2]+red[3]+red[4]+red[5]+red[6]+red[7];
    float mean = tot * (1.0f / DD);

    float4 d;
    d.x = v.x - mean; d.y = v.y - mean; d.z = v.z - mean; d.w = v.w - mean;
    float s2 = d.x*d.x + d.y*d.y + d.z*d.z + d.w*d.w;
    #pragma unroll
    for (int o = 16; o > 0; o >>= 1) s2 += __shfl_xor_sync(0xffffffffu, s2, o);
    __syncthreads();
    if ((tid & 31) == 0) red[tid >> 5] = s2;
    __syncthreads();
    float var = (red[0]+red[1]+red[2]+red[3]+red[4]+red[5]+red[6]+red[7]) * (1.0f / DD);
    float rstd = rsqrtf(var + 1e-5f);

    float4 g  = ((const float4*)gamma)[tid];
    float4 bb = ((const float4*)beta)[tid];
    __half2 h01 = __floats2half2_rn(d.x * rstd * g.x + bb.x, d.y * rstd * g.y + bb.y);
    __half2 h23 = __floats2half2_rn(d.z * rstd * g.z + bb.z, d.w * rstd * g.w + bb.w);
    uint2 u; u.x = *(uint32_t*)&h01; u.y = *(uint32_t*)&h23;
    ((uint2*)(g_xn + (size_t)row * DD))[tid] = u;
}

// ---------------------------------------------------------------------------
// fp16 tensor GEMM, cp.async double buffered.
// C[m,n] = sum_k A[m,k]*W[n,k]. 128x128 tile, BK=32 halfs, 8 warps (4m x 2n).
// mode 0: fused QKV (W = g_wt, bias = g_bias, n in [0,3072), scatter q/k/v)
// mode 1: output GEMM (W = g_wt+3*DD*DD, bias=bo, resid add, fp32 out)
// ---------------------------------------------------------------------------
#define KP2 20
#define MW2 (128 * KP2)                   // words per matrix buffer
#define GEMM_SMEM_BYTES (4 * MW2 * 4)     // 40960

__global__ __launch_bounds__(256, 2) void gemm_h(
    int mode,
    const float* __restrict__ bias_o,
    const float* __restrict__ resid,
    float* __restrict__ out)
{
    extern __shared__ uint32_t smem[];
    const __half* A = mode ? g_ao : g_xn;
    const __half* W = mode ? (g_wt + (size_t)3 * DD * DD) : g_wt;

    int tid = threadIdx.x;
    int wid = tid >> 5, lane = tid & 31;
    int m0 = blockIdx.y * 128;
    int n0 = blockIdx.x * 128;

    int wm = (wid & 3) * 32;
    int wn = (wid >> 2) * 64;
    int lr = lane >> 2;
    int lc = lane & 3;

    int srow[2], sc4[2];
    uint32_t sdstA[2], sdstB[2];
    uint32_t sbase = smem_u32(smem);
    #pragma unroll
    for (int i = 0; i < 2; i++) {
        int f = tid + i * 256;         // 0..511
        srow[i] = f >> 2;              // 0..127
        sc4[i]  = f & 3;               // 16B chunk within 64B row
        sdstA[i] = sbase + (srow[i] * KP2 + sc4[i] * 4) * 4;
        sdstB[i] = sdstA[i] + MW2 * 4;
    }

    float acc[2][8][4];
    #pragma unroll
    for (int tm = 0; tm < 2; tm++)
        #pragma unroll
        for (int tn = 0; tn < 8; tn++)
            #pragma unroll
            for (int c = 0; c < 4; c++) acc[tm][tn][c] = 0.0f;

    #pragma unroll
    for (int i = 0; i < 2; i++) {
        CP_ASYNC16(sdstA[i], A + (size_t)(m0 + srow[i]) * DD + sc4[i] * 8);
        CP_ASYNC16(sdstB[i], W + (size_t)(n0 + srow[i]) * DD + sc4[i] * 8);
    }
    CP_COMMIT();

    for (int kt = 0; kt < 32; kt++) {
        int buf = kt & 1;
        if (kt < 31) {
            int k0n = (kt + 1) * 32;
            uint32_t boff = (buf ^ 1) * 2 * MW2 * 4;
            #pragma unroll
            for (int i = 0; i < 2; i++) {
                CP_ASYNC16(sdstA[i] + boff, A + (size_t)(m0 + srow[i]) * DD + k0n + sc4[i] * 8);
                CP_ASYNC16(sdstB[i] + boff, W + (size_t)(n0 + srow[i]) * DD + k0n + sc4[i] * 8);
            }
            CP_COMMIT();
            CP_WAIT1();
        } else {
            CP_WAIT0();
        }
        __syncthreads();

        const uint32_t* As = smem + buf * 2 * MW2;
        const uint32_t* Bs = As + MW2;

        #pragma unroll
        for (int ks = 0; ks < 2; ks++) {
            int k0 = ks * 8;
            uint32_t af[2][4];
            #pragma unroll
            for (int tm = 0; tm < 2; tm++) {
                int base = (wm + tm * 16 + lr) * KP2 + k0 + lc;
                af[tm][0] = As[base];
                af[tm][1] = As[base + 8 * KP2];
                af[tm][2] = As[base + 4];
                af[tm][3] = As[base + 8 * KP2 + 4];
            }
            uint32_t bf[8][2];
            #pragma unroll
            for (int tn = 0; tn < 8; tn++) {
                int base = (wn + tn * 8 + lr) * KP2 + k0 + lc;
                bf[tn][0] = Bs[base];
                bf[tn][1] = Bs[base + 4];
            }
            #pragma unroll
            for (int tm = 0; tm < 2; tm++)
                #pragma unroll
                for (int tn = 0; tn < 8; tn++)
                    mma_f16(acc[tm][tn][0], acc[tm][tn][1], acc[tm][tn][2], acc[tm][tn][3],
                            af[tm][0], af[tm][1], af[tm][2], af[tm][3],
                            bf[tn][0], bf[tn][1]);
        }
        __syncthreads();
    }

    #pragma unroll
    for (int tm = 0; tm < 2; tm++) {
        #pragma unroll
        for (int half = 0; half < 2; half++) {
            int m = m0 + wm + tm * 16 + lr + half * 8;
            int bI = m >> 11, sI = m & (SS - 1);
            #pragma unroll
            for (int tn = 0; tn < 8; tn++) {
                int n = n0 + wn + tn * 8 + lc * 2;
                float r0 = acc[tm][tn][half*2+0];
                float r1 = acc[tm][tn][half*2+1];
                if (mode == 0) {
                    r0 += g_bias[n]; r1 += g_bias[n+1];
                    int sel = n >> 10;            // 0=q,1=k,2=v
                    int nn = n & (DD - 1);
                    int h = nn >> 6, hd = nn & 63;
                    if (sel < 2) {
                        __half2 hv = __floats2half2_rn(r0, r1);
                        __half* dst = (sel == 0) ? g_q : g_k;
                        size_t idx = ((size_t)(bI * HH + h) * SS + sI) * HDIM + hd;
                        *(__half2*)(dst + idx) = hv;
                    } else {
                        // V transposed: [B,H,Hd,S]
                        size_t base = ((size_t)(bI * HH + h) * HDIM + hd) * SS + sI;
                        g_v[base]      = __float2half_rn(r0);
                        g_v[base + SS] = __float2half_rn(r1);
                    }
                } else {
                    float2 bz = *(const float2*)(bias_o + n);
                    size_t idx = (size_t)m * DD + n;
                    float2 rv = *(const float2*)(resid + idx);
                    float2 r;
                    r.x = r0 + bz.x + rv.x;
                    r.y = r1 + bz.y + rv.y;
                    *(float2*)(out + idx) = r;
                }
            }
        }
    }
}

// ---------------------------------------------------------------------------
// fp16 tensor-core causal flash attention.
// 128 queries x 64 keys per iter, Hd=64, 8 warps (warp = 16 rows).
// grid: (S/128 = 16, B*H = 64)
// ---------------------------------------------------------------------------
#define KQ 36
#define ATTN_WORDS (128*KQ + 64*KQ + 64*KQ + 128*KQ + 64)
#define ATTN_SMEM_BYTES (ATTN_WORDS * 4)

__global__ __launch_bounds__(256) void attn_h(const float* __restrict__ mask)
{
    extern __shared__ uint32_t sm2[];
    uint32_t* Qs = sm2;                   // [128][KQ] half2 words, k packed
    uint32_t* Ks = Qs + 128*KQ;           // [64][KQ]  K[key][d]
    uint32_t* Vt = Ks + 64*KQ;            // [64][KQ]  V[d][key] (key pairs packed)
    uint32_t* Ps = Vt + 64*KQ;            // [128][KQ]
    float*    mv = (float*)(Ps + 128*KQ);

    int qb = (int)gridDim.x - 1 - (int)blockIdx.x;   // heavy blocks first
    int bh = blockIdx.y;
    int b = bh >> 4, h = bh & 15;

    const __half* Qg = g_q + ((size_t)bh * SS + qb * 128) * HDIM;
    const __half* Kg = g_k + (size_t)bh * SS * HDIM;
    const __half* Vg = g_v + (size_t)bh * HDIM * SS;   // [d][s]

    int tid = threadIdx.x;
    int wid = tid >> 5, lane = tid & 31;
    int lr = lane >> 2, lc = lane & 3;
    int wm = wid * 16;

    // stage Q: 128 rows x 32 words (uint4 = 4 words)
    #pragma unroll
    for (int i = 0; i < 4; i++) {
        int c = tid + i * 256;           // 0..1023
        int row = c >> 3, w4 = c & 7;
        uint4 t = *(const uint4*)(Qg + row * HDIM + w4 * 8);
        *(uint4*)(Qs + row * KQ + w4 * 4) = t;
    }

    float of[8][4];
    #pragma unroll
    for (int nt = 0; nt < 8; nt++)
        #pragma unroll
        for (int c = 0; c < 4; c++) of[nt][c] = 0.0f;
    float m0 = NEG_BIG, m1 = NEG_BIG, l0 = 0.0f, l1 = 0.0f;

    int row_g0 = qb * 128 + wm + lr;
    int row_g1 = row_g0 + 8;
    int arow0 = (wm + lr) * KQ;
    int arow1 = (wm + lr + 8) * KQ;

    int jbmax = 2 * qb + 1;
    for (int jb = 0; jb <= jbmax; jb++) {
        __syncthreads();
        // K rows: 64 x 8 uint4 = 512 chunks; Vt rows (d): 64 x 8 uint4
        #pragma unroll
        for (int i = 0; i < 2; i++) {
            int c = tid + i * 256;       // 0..511
            int row = c >> 3, w4 = c & 7;
            uint4 kt4 = *(const uint4*)(Kg + (size_t)(jb * 64 + row) * HDIM + w4 * 8);
            *(uint4*)(Ks + row * KQ + w4 * 4) = kt4;
            uint4 vt4 = *(const uint4*)(Vg + (size_t)row * SS + jb * 64 + w4 * 8);
            *(uint4*)(Vt + row * KQ + w4 * 4) = vt4;
        }
        if (tid < 64) mv[tid] = mask[b * SS + jb * 64 + tid];
        __syncthreads();

        // S = Q K^T
        float sf[8][4];
        #pragma unroll
        for (int nt = 0; nt < 8; nt++)
            #pragma unroll
            for (int c = 0; c < 4; c++) sf[nt][c] = 0.0f;

        #pragma unroll
        for (int ks = 0; ks < 4; ks++) {
            int k0 = ks * 8;
            uint32_t a0 = Qs[arow0 + k0 + lc];
            uint32_t a1 = Qs[arow1 + k0 + lc];
            uint32_t a2 = Qs[arow0 + k0 + lc + 4];
            uint32_t a3 = Qs[arow1 + k0 + lc + 4];
            #pragma unroll
            for (int nt = 0; nt < 8; nt++) {
                uint32_t b0 = Ks[(nt * 8 + lr) * KQ + k0 + lc];
                uint32_t b1 = Ks[(nt * 8 + lr) * KQ + k0 + lc + 4];
                mma_f16(sf[nt][0], sf[nt][1], sf[nt][2], sf[nt][3],
                        a0, a1, a2, a3, b0, b1);
            }
        }

        float rmax0 = NEG_BIG, rmax1 = NEG_BIG;
        #pragma unroll
        for (int nt = 0; nt < 8; nt++) {
            int cg = jb * 64 + nt * 8 + lc * 2;
            float pma = -10000.0f * (1.0f - mv[nt * 8 + lc * 2]);
            float pmb = -10000.0f * (1.0f - mv[nt * 8 + lc * 2 + 1]);
            float v0 = sf[nt][0] * 0.125f + pma; if (cg     > row_g0) v0 = NEG_BIG;
            float v1 = sf[nt][1] * 0.125f + pmb; if (cg + 1 > row_g0) v1 = NEG_BIG;
            float v2 = sf[nt][2] * 0.125f + pma; if (cg     > row_g1) v2 = NEG_BIG;
            float v3 = sf[nt][3] * 0.125f + pmb; if (cg + 1 > row_g1) v3 = NEG_BIG;
            sf[nt][0] = v0; sf[nt][1] = v1; sf[nt][2] = v2; sf[nt][3] = v3;
            rmax0 = fmaxf(rmax0, fmaxf(v0, v1));
            rmax1 = fmaxf(rmax1, fmaxf(v2, v3));
        }
        rmax0 = fmaxf(rmax0, __shfl_xor_sync(0xffffffffu, rmax0, 1));
        rmax0 = fmaxf(rmax0, __shfl_xor_sync(0xffffffffu, rmax0, 2));
        rmax1 = fmaxf(rmax1, __shfl_xor_sync(0xffffffffu, rmax1, 1));
        rmax1 = fmaxf(rmax1, __shfl_xor_sync(0xffffffffu, rmax1, 2));

        float mn0 = fmaxf(m0, rmax0), mn1 = fmaxf(m1, rmax1);
        float sc0 = __expf(m0 - mn0), sc1 = __expf(m1 - mn1);
        m0 = mn0; m1 = mn1;

        float ls0 = 0.0f, ls1 = 0.0f;
        #pragma unroll
        for (int nt = 0; nt < 8; nt++) {
            float p0 = __expf(sf[nt][0] - mn0);
            float p1 = __expf(sf[nt][1] - mn0);
            float p2 = __expf(sf[nt][2] - mn1);
            float p3 = __expf(sf[nt][3] - mn1);
            ls0 += p0 + p1; ls1 += p2 + p3;
            __half2 w0 = __floats2half2_rn(p0, p1);
            __half2 w1 = __floats2half2_rn(p2, p3);
            Ps[arow0 + nt * 4 + lc] = *(uint32_t*)&w0;
            Ps[arow1 + nt * 4 + lc] = *(uint32_t*)&w1;
            of[nt][0] *= sc0; of[nt][1] *= sc0;
            of[nt][2] *= sc1; of[nt][3] *= sc1;
        }
        ls0 += __shfl_xor_sync(0xffffffffu, ls0, 1);
        ls0 += __shfl_xor_sync(0xffffffffu, ls0, 2);
        ls1 += __shfl_xor_sync(0xffffffffu, ls1, 1);
        ls1 += __shfl_xor_sync(0xffffffffu, ls1, 2);
        l0 = l0 * sc0 + ls0;
        l1 = l1 * sc1 + ls1;

        __syncwarp();

        // O += P V   (A = P [q][key], B = Vt [d][key] col-major over key)
        #pragma unroll
        for (int ks = 0; ks < 4; ks++) {
            int k0 = ks * 8;
            uint32_t a0 = Ps[arow0 + k0 + lc];
            uint32_t a1 = Ps[arow1 + k0 + lc];
            uint32_t a2 = Ps[arow0 + k0 + lc + 4];
            uint32_t a3 = Ps[arow1 + k0 + lc + 4];
            #pragma unroll
            for (int nt = 0; nt < 8; nt++) {
                uint32_t b0 = Vt[(nt * 8 + lr) * KQ + k0 + lc];
                uint32_t b1 = Vt[(nt * 8 + lr) * KQ + k0 + lc + 4];
                mma_f16(of[nt][0], of[nt][1], of[nt][2], of[nt][3],
                        a0, a1, a2, a3, b0, b1);
            }
        }
    }

    float inv0 = 1.0f / l0, inv1 = 1.0f / l1;
    size_t r0w = ((size_t)b * SS + qb * 128 + wm + lr) * DD + h * HDIM;
    size_t r1w = r0w + (size_t)8 * DD;
    #pragma unroll
    for (int nt = 0; nt < 8; nt++) {
        __half2 o0 = __floats2half2_rn(of[nt][0] * inv0, of[nt][1] * inv0);
        __half2 o1 = __floats2half2_rn(of[nt][2] * inv1, of[nt][3] * inv1);
        *(__half2*)(g_ao + r0w + nt * 8 + lc * 2) = o0;
        *(__half2*)(g_ao + r1w + nt * 8 + lc * 2) = o1;
    }
}

// ---------------------------------------------------------------------------
extern "C" void kernel_launch(void* const* d_in, const int* in_sizes, int n_in,
                              void* d_out, int out_size)
{
    const float* x     = (const float*)d_in[0];
    const float* amask = (const float*)d_in[1];
    const float* Wq    = (const float*)d_in[2];
    const float* bq    = (const float*)d_in[3];
    const float* Wk    = (const float*)d_in[4];
    const float* bk    = (const float*)d_in[5];
    const float* Wv    = (const float*)d_in[6];
    const float* bv    = (const float*)d_in[7];
    const float* Wo    = (const float*)d_in[8];
    const float* bo    = (const float*)d_in[9];
    const float* gam   = (const float*)d_in[10];
    const float* bet   = (const float*)d_in[11];
    float* out = (float*)d_out;

    cudaFuncSetAttribute(attn_h,
                         cudaFuncAttributeMaxDynamicSharedMemorySize,
                         ATTN_SMEM_BYTES);
    cudaFuncSetAttribute(gemm_h,
                         cudaFuncAttributeMaxDynamicSharedMemorySize,
                         GEMM_SMEM_BYTES);

    int cvtg = DD * DD / 4 / 256;   // 1024
    cvtw_kernel<<<cvtg, 256>>>(Wq, 0);
    cvtw_kernel<<<cvtg, 256>>>(Wk, 1);
    cvtw_kernel<<<cvtg, 256>>>(Wv, 2);
    cvtw_kernel<<<cvtg, 256>>>(Wo, 3);
    bias_kernel<<<12, 256>>>(bq, bk, bv);

    ln_kernel<<<MM, 256>>>(x, gam, bet);

    dim3 qkvgrid(3*DD/128, MM/128);   // (24, 64)
    gemm_h<<<qkvgrid, 256, GEMM_SMEM_BYTES>>>(0, nullptr, nullptr, nullptr);

    dim3 agrid(SS/128, BB*HH);        // (16, 64)
    attn_h<<<agrid, 256, ATTN_SMEM_BYTES>>>(amask);

    dim3 ogrid(DD/128, MM/128);       // (8, 64)
    gemm_h<<<ogrid, 256, GEMM_SMEM_BYTES>>>(1, bo, x, out);
}